// round 1
// baseline (speedup 1.0000x reference)
#include <cuda_runtime.h>
#include <math.h>

#define Bc   64
#define Pc   100
#define Nc   1000
#define EMBc 128
#define Hc   8
#define Dc   16

// ---- scratch (no allocations allowed; __device__ globals) ----
__device__ __align__(16) float g_K[Bc * Nc * EMBc];     // (B,N,128) heads packed h*16+d
__device__ __align__(16) float g_V[Bc * Nc * EMBc];
__device__ __align__(16) float g_Q[Bc * Pc * EMBc];
__device__ __align__(16) float g_O[Bc * Pc * EMBc];     // attention out concat
__device__ __align__(16) float g_MH[Bc * Pc * EMBc];    // mh_atten_out

// constants
constexpr double X218   = 3.814697265625e-06;           // 2^((100-1000)/50) = 2^-18
constexpr float  A_COEF = (float)(1.0 / (1.0 + X218));
constexpr float  B_COEF = (float)(1.0 - 1.0 / (1.0 + X218));
constexpr float  INV_SQRT_EMB = 0.08838834764831845f;   // 1/sqrt(128)

// ============================================================================
// Kernel 1: K = E @ Wk, V = E @ Wv   (rows = B*N = 64000, 32 rows per block)
// ============================================================================
__global__ void kv_kernel(const float* __restrict__ E,
                          const float* __restrict__ Wk,
                          const float* __restrict__ Wv) {
    __shared__ __align__(16) float As[128][36];   // [k][row], padded; row-base 144B (16B-aligned)
    const int r0  = blockIdx.x * 32;
    const int tid = threadIdx.x;

    #pragma unroll
    for (int j = 0; j < 16; ++j) {
        int l = tid + j * 256;
        int row = l >> 7, k = l & 127;
        As[k][row] = E[(r0 + row) * 128 + k];
    }
    __syncthreads();

    const int c  = tid & 127;
    const int rg = tid >> 7;                      // 0 or 1; uniform within warp
    float accK[16], accV[16];
    #pragma unroll
    for (int i = 0; i < 16; ++i) { accK[i] = 0.f; accV[i] = 0.f; }

    #pragma unroll 4
    for (int k = 0; k < 128; ++k) {
        float wk = Wk[k * 128 + c];
        float wv = Wv[k * 128 + c];
        float a[16];
        const float4* ap = (const float4*)&As[k][rg * 16];   // broadcast within warp
        ((float4*)a)[0] = ap[0]; ((float4*)a)[1] = ap[1];
        ((float4*)a)[2] = ap[2]; ((float4*)a)[3] = ap[3];
        #pragma unroll
        for (int i = 0; i < 16; ++i) {
            accK[i] = fmaf(a[i], wk, accK[i]);
            accV[i] = fmaf(a[i], wv, accV[i]);
        }
    }

    #pragma unroll
    for (int i = 0; i < 16; ++i) {
        int row = r0 + rg * 16 + i;
        g_K[row * 128 + c] = accK[i];
        g_V[row * 128 + c] = accV[i];
    }
}

// ============================================================================
// Kernel 2: Q = concat(eln, load, time) @ Wq   (rows = B*P = 6400, 16/block)
// ============================================================================
__global__ void q_kernel(const float* __restrict__ eln,
                         const float* __restrict__ loadv,
                         const float* __restrict__ timev,
                         const float* __restrict__ Wq) {
    __shared__ __align__(16) float sA[130][16];   // [k][row]
    const int r0  = blockIdx.x * 16;
    const int tid = threadIdx.x;

    for (int l = tid; l < 130 * 16; l += 128) {
        int k = l >> 4, r = l & 15;
        int g = r0 + r;
        float v;
        if (k < 128)       v = eln[g * 128 + k];
        else if (k == 128) v = loadv[g];
        else               v = timev[g];
        sA[k][r] = v;
    }
    __syncthreads();

    const int c = tid;
    float acc[16];
    #pragma unroll
    for (int i = 0; i < 16; ++i) acc[i] = 0.f;

    for (int k = 0; k < 130; ++k) {
        float w = Wq[k * 128 + c];
        float a[16];
        const float4* ap = (const float4*)sA[k];
        ((float4*)a)[0] = ap[0]; ((float4*)a)[1] = ap[1];
        ((float4*)a)[2] = ap[2]; ((float4*)a)[3] = ap[3];
        #pragma unroll
        for (int i = 0; i < 16; ++i) acc[i] = fmaf(a[i], w, acc[i]);
    }
    #pragma unroll
    for (int i = 0; i < 16; ++i) g_Q[(r0 + i) * 128 + c] = acc[i];
}

// ============================================================================
// Kernel 3: multi-head attention, online softmax. block = (b,h); thread = p.
// ============================================================================
__global__ void attn_kernel(const float* __restrict__ ninf) {
    const int b   = blockIdx.x >> 3;
    const int h   = blockIdx.x & 7;
    const int tid = threadIdx.x;
    const int p   = tid;

    __shared__ __align__(16) float Kt[64][16];
    __shared__ __align__(16) float Vt[64][16];

    float q[16];
    #pragma unroll
    for (int i = 0; i < 16; ++i) q[i] = 0.f;
    if (p < 100) {
        const float4* qp = (const float4*)(g_Q + (b * 100 + p) * 128 + h * 16);
        ((float4*)q)[0] = qp[0]; ((float4*)q)[1] = qp[1];
        ((float4*)q)[2] = qp[2]; ((float4*)q)[3] = qp[3];
    }
    const float* maskrow = ninf + (p < 100 ? (b * 100 + p) * 1000 : 0);

    float m = -INFINITY, lsum = 0.f;
    float acc[16];
    #pragma unroll
    for (int i = 0; i < 16; ++i) acc[i] = 0.f;

    for (int n0 = 0; n0 < 1000; n0 += 64) {
        const int cnt = min(64, 1000 - n0);
        __syncthreads();
        for (int l = tid; l < cnt * 4; l += 128) {
            int n = l >> 2, d4 = l & 3;
            const float4* kp = (const float4*)(g_K + (b * 1000 + n0 + n) * 128 + h * 16);
            const float4* vp = (const float4*)(g_V + (b * 1000 + n0 + n) * 128 + h * 16);
            ((float4*)Kt[n])[d4] = kp[d4];
            ((float4*)Vt[n])[d4] = vp[d4];
        }
        __syncthreads();

        if (p < 100) {
            for (int j = 0; j < cnt; ++j) {
                float kk[16];
                const float4* kp = (const float4*)Kt[j];     // broadcast
                ((float4*)kk)[0] = kp[0]; ((float4*)kk)[1] = kp[1];
                ((float4*)kk)[2] = kp[2]; ((float4*)kk)[3] = kp[3];
                float s = 0.f;
                #pragma unroll
                for (int i = 0; i < 16; ++i) s = fmaf(q[i], kk[i], s);
                s = s * 0.25f + maskrow[n0 + j];

                float vv[16];
                const float4* vp = (const float4*)Vt[j];
                ((float4*)vv)[0] = vp[0]; ((float4*)vv)[1] = vp[1];
                ((float4*)vv)[2] = vp[2]; ((float4*)vv)[3] = vp[3];

                if (s <= m) {                                  // common path
                    float e = __expf(s - m);
                    lsum += e;
                    #pragma unroll
                    for (int i = 0; i < 16; ++i) acc[i] = fmaf(e, vv[i], acc[i]);
                } else {                                       // rare rescale; first iter: corr=0
                    float corr = __expf(m - s);
                    m = s;
                    lsum = fmaf(lsum, corr, 1.f);
                    #pragma unroll
                    for (int i = 0; i < 16; ++i) acc[i] = fmaf(acc[i], corr, vv[i]);
                }
            }
        }
    }

    if (p < 100) {
        float inv = 1.f / lsum;
        float* op = g_O + (b * 100 + p) * 128 + h * 16;
        #pragma unroll
        for (int i = 0; i < 16; ++i) op[i] = acc[i] * inv;
    }
}

// ============================================================================
// Kernel 4: MH = O @ Wc + bc   (rows = 6400, 16/block)
// ============================================================================
__global__ void mh_kernel(const float* __restrict__ Wc,
                          const float* __restrict__ bc) {
    __shared__ __align__(16) float sA[128][16];
    const int r0  = blockIdx.x * 16;
    const int tid = threadIdx.x;

    for (int l = tid; l < 128 * 16; l += 128) {
        int k = l >> 4, r = l & 15;
        sA[k][r] = g_O[(r0 + r) * 128 + k];
    }
    __syncthreads();

    const int c = tid;
    const float bias = bc[c];
    float acc[16];
    #pragma unroll
    for (int i = 0; i < 16; ++i) acc[i] = bias;

    for (int k = 0; k < 128; ++k) {
        float w = Wc[k * 128 + c];
        float a[16];
        const float4* ap = (const float4*)sA[k];
        ((float4*)a)[0] = ap[0]; ((float4*)a)[1] = ap[1];
        ((float4*)a)[2] = ap[2]; ((float4*)a)[3] = ap[3];
        #pragma unroll
        for (int i = 0; i < 16; ++i) acc[i] = fmaf(a[i], w, acc[i]);
    }
    #pragma unroll
    for (int i = 0; i < 16; ++i) g_MH[(r0 + i) * 128 + c] = acc[i];
}

// ============================================================================
// Kernel 5: score2 = MH @ E^T, fused heuristic/noise/tanh/mask -> out
// grid (8 n-tiles x 2 p-tiles x 64 b), block 256 = (tx 32 n, ty 8 p)
// ============================================================================
__global__ void score_kernel(const float* __restrict__ Enodes,
                             const float* __restrict__ cur_dist,
                             const float* __restrict__ ninf,
                             const float* __restrict__ noise,
                             float* __restrict__ out) {
    const int b   = blockIdx.z;
    const int p0  = blockIdx.y * 50;
    const int n0  = blockIdx.x * 128;
    const int tid = threadIdx.x;
    const int tx  = tid & 31, ty = tid >> 5;     // warp = fixed ty -> Ms broadcast

    __shared__ float Es[32][129];                // [k][n], pad -> conflict-free
    __shared__ float Ms[32][56];                 // [k][p], cols 50..55 zero-padded

    float acc[7][4];
    #pragma unroll
    for (int i = 0; i < 7; ++i)
        #pragma unroll
        for (int j = 0; j < 4; ++j) acc[i][j] = 0.f;

    for (int kc = 0; kc < 128; kc += 32) {
        __syncthreads();
        for (int l = tid; l < 32 * 128; l += 256) {
            int n = l >> 5, k = l & 31;
            Es[k][n] = (n0 + n < 1000) ? Enodes[(b * 1000 + n0 + n) * 128 + kc + k] : 0.f;
        }
        for (int l = tid; l < 32 * 56; l += 256) {
            int pp = l >> 5, k = l & 31;
            Ms[k][pp] = (pp < 50) ? g_MH[(b * 100 + p0 + pp) * 128 + kc + k] : 0.f;
        }
        __syncthreads();

        #pragma unroll 4
        for (int k = 0; k < 32; ++k) {
            float mv[7], ev[4];
            #pragma unroll
            for (int i = 0; i < 7; ++i) mv[i] = Ms[k][ty + 8 * i];
            #pragma unroll
            for (int j = 0; j < 4; ++j) ev[j] = Es[k][tx + 32 * j];
            #pragma unroll
            for (int i = 0; i < 7; ++i)
                #pragma unroll
                for (int j = 0; j < 4; ++j)
                    acc[i][j] = fmaf(mv[i], ev[j], acc[i][j]);
        }
    }

    #pragma unroll
    for (int i = 0; i < 7; ++i) {
        int pl = ty + 8 * i;
        if (pl < 50) {
            int p = p0 + pl;
            #pragma unroll
            for (int j = 0; j < 4; ++j) {
                int n = n0 + tx + 32 * j;
                if (n < 1000) {
                    int idx = (b * 100 + p) * 1000 + n;
                    float cd   = cur_dist[idx];
                    float heur = -logf(fmaf(2.f, cd, 1e-6f));
                    float s    = acc[i][j] * INV_SQRT_EMB + A_COEF * heur + B_COEF * noise[idx];
                    out[idx]   = 10.f * tanhf(s) + ninf[idx];
                }
            }
        }
    }
}

// ============================================================================
// Kernel 6: in-place row softmax over N=1000 (out holds masked scores)
// ============================================================================
__global__ void softmax_kernel(float* __restrict__ out) {
    const int row = blockIdx.x;
    const int tid = threadIdx.x;
    float* sp = out + row * 1000;

    float v[4];
    #pragma unroll
    for (int t = 0; t < 4; ++t) {
        int n = tid + t * 256;
        v[t] = (n < 1000) ? sp[n] : -INFINITY;
    }
    float m = fmaxf(fmaxf(v[0], v[1]), fmaxf(v[2], v[3]));
    #pragma unroll
    for (int o = 16; o; o >>= 1) m = fmaxf(m, __shfl_xor_sync(0xffffffffu, m, o));

    __shared__ float smax[8];
    __shared__ float ssum[8];
    if ((tid & 31) == 0) smax[tid >> 5] = m;
    __syncthreads();
    float M = smax[0];
    #pragma unroll
    for (int w = 1; w < 8; ++w) M = fmaxf(M, smax[w]);

    float e[4], lsum = 0.f;
    #pragma unroll
    for (int t = 0; t < 4; ++t) { e[t] = __expf(v[t] - M); lsum += e[t]; }
    #pragma unroll
    for (int o = 16; o; o >>= 1) lsum += __shfl_xor_sync(0xffffffffu, lsum, o);
    if ((tid & 31) == 0) ssum[tid >> 5] = lsum;
    __syncthreads();
    float S = 0.f;
    #pragma unroll
    for (int w = 0; w < 8; ++w) S += ssum[w];

    float inv = 1.f / S;
    #pragma unroll
    for (int t = 0; t < 4; ++t) {
        int n = tid + t * 256;
        if (n < 1000) sp[n] = e[t] * inv;
    }
}

// ============================================================================
extern "C" void kernel_launch(void* const* d_in, const int* in_sizes, int n_in,
                              void* d_out, int out_size) {
    const float* eln      = (const float*)d_in[0];
    const float* loadv    = (const float*)d_in[1];
    const float* timev    = (const float*)d_in[2];
    const float* cur_dist = (const float*)d_in[3];
    const float* ninf     = (const float*)d_in[4];
    const float* noise    = (const float*)d_in[5];
    const float* Enodes   = (const float*)d_in[6];
    const float* Wq       = (const float*)d_in[7];
    const float* Wk       = (const float*)d_in[8];
    const float* Wv       = (const float*)d_in[9];
    const float* Wc       = (const float*)d_in[10];
    const float* bc       = (const float*)d_in[11];
    float* out = (float*)d_out;

    kv_kernel<<<2000, 256>>>(Enodes, Wk, Wv);
    q_kernel<<<400, 128>>>(eln, loadv, timev, Wq);
    attn_kernel<<<512, 128>>>(ninf);
    mh_kernel<<<400, 128>>>(Wc, bc);
    score_kernel<<<dim3(8, 2, 64), 256>>>(Enodes, cur_dist, ninf, noise, out);
    softmax_kernel<<<6400, 256>>>(out);
}

// round 2
// speedup vs baseline: 1.4847x; 1.4847x over previous
#include <cuda_runtime.h>
#include <math.h>

#define Bc   64
#define Pc   100
#define Nc   1000
#define EMBc 128

// ---- scratch (no allocations allowed; __device__ globals) ----
__device__ __align__(16) float g_K[Bc * Nc * EMBc];
__device__ __align__(16) float g_V[Bc * Nc * EMBc];
__device__ __align__(16) float g_Q[Bc * Pc * EMBc];
__device__ __align__(16) float g_O[Bc * Pc * EMBc];
__device__ __align__(16) float g_MH[Bc * Pc * EMBc];

constexpr double X218   = 3.814697265625e-06;           // 2^((100-1000)/50)
constexpr float  A_COEF = (float)(1.0 / (1.0 + X218));
constexpr float  B_COEF = (float)(1.0 - 1.0 / (1.0 + X218));
constexpr float  INV_SQRT_EMB = 0.08838834764831845f;   // 1/sqrt(128)

// ---- packed fp32x2 helpers (sm_103a FFMA2 path, only reachable via PTX) ----
typedef unsigned long long u64t;
__device__ __forceinline__ u64t fma2(u64t a, u64t b, u64t c) {
    u64t d; asm("fma.rn.f32x2 %0, %1, %2, %3;" : "=l"(d) : "l"(a), "l"(b), "l"(c)); return d;
}
__device__ __forceinline__ u64t mul2(u64t a, u64t b) {
    u64t d; asm("mul.rn.f32x2 %0, %1, %2;" : "=l"(d) : "l"(a), "l"(b)); return d;
}
__device__ __forceinline__ u64t add2(u64t a, u64t b) {
    u64t d; asm("add.rn.f32x2 %0, %1, %2;" : "=l"(d) : "l"(a), "l"(b)); return d;
}
__device__ __forceinline__ u64t splat2(float x) {
    u64t d; asm("mov.b64 %0, {%1, %1};" : "=l"(d) : "f"(x)); return d;
}
__device__ __forceinline__ float2 unpack2(u64t v) {
    float2 r; asm("mov.b64 {%0, %1}, %2;" : "=f"(r.x), "=f"(r.y) : "l"(v)); return r;
}

// ============================================================================
// Kernel 1: K = E @ Wk, V = E @ Wv.  C-tile 64x128, micro 4x8, f32x2 packed.
// ============================================================================
__global__ void __launch_bounds__(256, 2)
kv_kernel(const float* __restrict__ E,
          const float* __restrict__ Wk,
          const float* __restrict__ Wv) {
    __shared__ float As[16][64];
    __shared__ float Wks[16][128];
    __shared__ float Wvs[16][128];
    const int tid = threadIdx.x;
    const int R0  = blockIdx.x * 64;
    const int tx  = tid & 15;        // col group: cols tx*8 .. tx*8+7
    const int ty  = tid >> 4;        // row group: rows ty*4 .. ty*4+3
    const int arow = tid >> 2, akq = (tid & 3) * 4;

    u64t accK[16], accV[16];
    #pragma unroll
    for (int i = 0; i < 16; ++i) { accK[i] = 0ull; accV[i] = 0ull; }

    for (int kc = 0; kc < 128; kc += 16) {
        __syncthreads();
        float4 av = *(const float4*)(E + (R0 + arow) * 128 + kc + akq);
        As[akq + 0][arow] = av.x; As[akq + 1][arow] = av.y;
        As[akq + 2][arow] = av.z; As[akq + 3][arow] = av.w;
        const int off = tid * 8;
        *(float4*)(&Wks[0][0] + off)     = *(const float4*)(Wk + kc * 128 + off);
        *(float4*)(&Wks[0][0] + off + 4) = *(const float4*)(Wk + kc * 128 + off + 4);
        *(float4*)(&Wvs[0][0] + off)     = *(const float4*)(Wv + kc * 128 + off);
        *(float4*)(&Wvs[0][0] + off + 4) = *(const float4*)(Wv + kc * 128 + off + 4);
        __syncthreads();

        #pragma unroll 4
        for (int k = 0; k < 16; ++k) {
            float4 a = *(const float4*)&As[k][ty * 4];
            u64t a0 = splat2(a.x), a1 = splat2(a.y), a2 = splat2(a.z), a3 = splat2(a.w);
            const ulonglong2* wkp = (const ulonglong2*)&Wks[k][tx * 8];
            ulonglong2 wk0 = wkp[0], wk1 = wkp[1];
            const ulonglong2* wvp = (const ulonglong2*)&Wvs[k][tx * 8];
            ulonglong2 wv0 = wvp[0], wv1 = wvp[1];

            accK[0]  = fma2(a0, wk0.x, accK[0]);  accK[1]  = fma2(a0, wk0.y, accK[1]);
            accK[2]  = fma2(a0, wk1.x, accK[2]);  accK[3]  = fma2(a0, wk1.y, accK[3]);
            accK[4]  = fma2(a1, wk0.x, accK[4]);  accK[5]  = fma2(a1, wk0.y, accK[5]);
            accK[6]  = fma2(a1, wk1.x, accK[6]);  accK[7]  = fma2(a1, wk1.y, accK[7]);
            accK[8]  = fma2(a2, wk0.x, accK[8]);  accK[9]  = fma2(a2, wk0.y, accK[9]);
            accK[10] = fma2(a2, wk1.x, accK[10]); accK[11] = fma2(a2, wk1.y, accK[11]);
            accK[12] = fma2(a3, wk0.x, accK[12]); accK[13] = fma2(a3, wk0.y, accK[13]);
            accK[14] = fma2(a3, wk1.x, accK[14]); accK[15] = fma2(a3, wk1.y, accK[15]);

            accV[0]  = fma2(a0, wv0.x, accV[0]);  accV[1]  = fma2(a0, wv0.y, accV[1]);
            accV[2]  = fma2(a0, wv1.x, accV[2]);  accV[3]  = fma2(a0, wv1.y, accV[3]);
            accV[4]  = fma2(a1, wv0.x, accV[4]);  accV[5]  = fma2(a1, wv0.y, accV[5]);
            accV[6]  = fma2(a1, wv1.x, accV[6]);  accV[7]  = fma2(a1, wv1.y, accV[7]);
            accV[8]  = fma2(a2, wv0.x, accV[8]);  accV[9]  = fma2(a2, wv0.y, accV[9]);
            accV[10] = fma2(a2, wv1.x, accV[10]); accV[11] = fma2(a2, wv1.y, accV[11]);
            accV[12] = fma2(a3, wv0.x, accV[12]); accV[13] = fma2(a3, wv0.y, accV[13]);
            accV[14] = fma2(a3, wv1.x, accV[14]); accV[15] = fma2(a3, wv1.y, accV[15]);
        }
    }

    #pragma unroll
    for (int r = 0; r < 4; ++r) {
        float* dk = g_K + (R0 + ty * 4 + r) * 128 + tx * 8;
        float* dv = g_V + (R0 + ty * 4 + r) * 128 + tx * 8;
        ulonglong2 t;
        t.x = accK[r * 4 + 0]; t.y = accK[r * 4 + 1]; ((ulonglong2*)dk)[0] = t;
        t.x = accK[r * 4 + 2]; t.y = accK[r * 4 + 3]; ((ulonglong2*)dk)[1] = t;
        t.x = accV[r * 4 + 0]; t.y = accV[r * 4 + 1]; ((ulonglong2*)dv)[0] = t;
        t.x = accV[r * 4 + 2]; t.y = accV[r * 4 + 3]; ((ulonglong2*)dv)[1] = t;
    }
}

// ============================================================================
// Kernel 2: Q = concat(eln, load, time) @ Wq   (rows = 6400, 16/block)
// ============================================================================
__global__ void q_kernel(const float* __restrict__ eln,
                         const float* __restrict__ loadv,
                         const float* __restrict__ timev,
                         const float* __restrict__ Wq) {
    __shared__ __align__(16) float sA[130][16];
    const int r0  = blockIdx.x * 16;
    const int tid = threadIdx.x;

    for (int l = tid; l < 130 * 16; l += 128) {
        int k = l >> 4, r = l & 15;
        int g = r0 + r;
        float v;
        if (k < 128)       v = eln[g * 128 + k];
        else if (k == 128) v = loadv[g];
        else               v = timev[g];
        sA[k][r] = v;
    }
    __syncthreads();

    const int c = tid;
    float acc[16];
    #pragma unroll
    for (int i = 0; i < 16; ++i) acc[i] = 0.f;

    for (int k = 0; k < 130; ++k) {
        float w = Wq[k * 128 + c];
        float a[16];
        const float4* ap = (const float4*)sA[k];
        ((float4*)a)[0] = ap[0]; ((float4*)a)[1] = ap[1];
        ((float4*)a)[2] = ap[2]; ((float4*)a)[3] = ap[3];
        #pragma unroll
        for (int i = 0; i < 16; ++i) acc[i] = fmaf(a[i], w, acc[i]);
    }
    #pragma unroll
    for (int i = 0; i < 16; ++i) g_Q[(r0 + i) * 128 + c] = acc[i];
}

// ============================================================================
// Kernel 3: attention. block=(b,h), thread=p. No online max (scores bounded;
// softmax shift-invariant; masked -> __expf(-1e9)=0). Mask staged in smem.
// ============================================================================
#define TN 100
__global__ void __launch_bounds__(128, 4)
attn_kernel(const float* __restrict__ ninf) {
    const int b   = blockIdx.x >> 3;
    const int h   = blockIdx.x & 7;
    const int tid = threadIdx.x;

    __shared__ __align__(16) float Kt[TN][16];
    __shared__ __align__(16) float Vt[TN][16];
    __shared__ float Ms[100][TN + 1];

    u64t q2[8];
    #pragma unroll
    for (int i = 0; i < 8; ++i) q2[i] = 0ull;
    if (tid < 100) {
        const ulonglong2* qp = (const ulonglong2*)(g_Q + (b * 100 + tid) * 128 + h * 16);
        u64t qs = splat2(0.25f);                      // fold 1/sqrt(D) into q
        #pragma unroll
        for (int i = 0; i < 4; ++i) {
            ulonglong2 t = qp[i];
            q2[2 * i]     = mul2(t.x, qs);
            q2[2 * i + 1] = mul2(t.y, qs);
        }
    }

    u64t acc2[8];
    #pragma unroll
    for (int i = 0; i < 8; ++i) acc2[i] = 0ull;
    float lsum = 0.f;

    const float* Kbase = g_K + b * 1000 * 128 + h * 16;
    const float* Vbase = g_V + b * 1000 * 128 + h * 16;
    const float* Mbase = ninf + b * 100 * 1000;

    for (int n0 = 0; n0 < 1000; n0 += TN) {
        __syncthreads();
        for (int l = tid; l < TN * 4; l += 128) {
            int n = l >> 2, qd = l & 3;
            ((float4*)Kt[n])[qd] = *(const float4*)(Kbase + (n0 + n) * 128 + qd * 4);
            ((float4*)Vt[n])[qd] = *(const float4*)(Vbase + (n0 + n) * 128 + qd * 4);
        }
        for (int l = tid; l < 100 * 25; l += 128) {
            int p = l / 25, jq = (l % 25) * 4;
            float4 mv = *(const float4*)(Mbase + p * 1000 + n0 + jq);
            Ms[p][jq + 0] = mv.x; Ms[p][jq + 1] = mv.y;
            Ms[p][jq + 2] = mv.z; Ms[p][jq + 3] = mv.w;
        }
        __syncthreads();

        if (tid < 100) {
            #pragma unroll 4
            for (int j = 0; j < TN; ++j) {
                const ulonglong2* kp = (const ulonglong2*)Kt[j];
                ulonglong2 ka = kp[0], kb = kp[1], kc2 = kp[2], kd = kp[3];
                u64t d0 = mul2(q2[0], ka.x);
                u64t d1 = mul2(q2[1], ka.y);
                d0 = fma2(q2[2], kb.x,  d0);
                d1 = fma2(q2[3], kb.y,  d1);
                d0 = fma2(q2[4], kc2.x, d0);
                d1 = fma2(q2[5], kc2.y, d1);
                d0 = fma2(q2[6], kd.x,  d0);
                d1 = fma2(q2[7], kd.y,  d1);
                float2 sv = unpack2(add2(d0, d1));
                float s = sv.x + sv.y + Ms[tid][j];
                float e = __expf(s);
                lsum += e;
                u64t e2 = splat2(e);
                const ulonglong2* vp = (const ulonglong2*)Vt[j];
                ulonglong2 va = vp[0], vb = vp[1], vc = vp[2], vd = vp[3];
                acc2[0] = fma2(e2, va.x, acc2[0]); acc2[1] = fma2(e2, va.y, acc2[1]);
                acc2[2] = fma2(e2, vb.x, acc2[2]); acc2[3] = fma2(e2, vb.y, acc2[3]);
                acc2[4] = fma2(e2, vc.x, acc2[4]); acc2[5] = fma2(e2, vc.y, acc2[5]);
                acc2[6] = fma2(e2, vd.x, acc2[6]); acc2[7] = fma2(e2, vd.y, acc2[7]);
            }
        }
    }

    if (tid < 100) {
        u64t inv2 = splat2(1.f / lsum);
        float* op = g_O + (b * 100 + tid) * 128 + h * 16;
        #pragma unroll
        for (int i = 0; i < 4; ++i) {
            ulonglong2 t;
            t.x = mul2(acc2[2 * i], inv2);
            t.y = mul2(acc2[2 * i + 1], inv2);
            ((ulonglong2*)op)[i] = t;
        }
    }
}

// ============================================================================
// Kernel 4: MH = O @ Wc + bc.  C-tile 32x128, micro 2x8, f32x2.
// ============================================================================
__global__ void __launch_bounds__(256, 4)
mh_kernel(const float* __restrict__ Wc, const float* __restrict__ bc) {
    __shared__ float As[32][36];
    __shared__ float Ws[32][128];
    const int tid = threadIdx.x;
    const int R0  = blockIdx.x * 32;
    const int tx  = tid & 15, ty = tid >> 4;

    u64t acc[8];
    {
        const ulonglong2* bp = (const ulonglong2*)(bc + tx * 8);
        ulonglong2 b0 = bp[0], b1 = bp[1];
        acc[0] = b0.x; acc[1] = b0.y; acc[2] = b1.x; acc[3] = b1.y;
        acc[4] = b0.x; acc[5] = b0.y; acc[6] = b1.x; acc[7] = b1.y;
    }

    for (int kc = 0; kc < 128; kc += 32) {
        __syncthreads();
        for (int l = tid; l < 1024; l += 256) {
            int row = l >> 5, k = l & 31;
            As[k][row] = g_O[(R0 + row) * 128 + kc + k];
        }
        const int off = tid * 16;
        #pragma unroll
        for (int i = 0; i < 4; ++i)
            *(float4*)(&Ws[0][0] + off + i * 4) = *(const float4*)(Wc + kc * 128 + off + i * 4);
        __syncthreads();

        #pragma unroll 4
        for (int k = 0; k < 32; ++k) {
            float2 a = *(const float2*)&As[k][ty * 2];
            u64t a0 = splat2(a.x), a1 = splat2(a.y);
            const ulonglong2* wp = (const ulonglong2*)&Ws[k][tx * 8];
            ulonglong2 w0 = wp[0], w1 = wp[1];
            acc[0] = fma2(a0, w0.x, acc[0]); acc[1] = fma2(a0, w0.y, acc[1]);
            acc[2] = fma2(a0, w1.x, acc[2]); acc[3] = fma2(a0, w1.y, acc[3]);
            acc[4] = fma2(a1, w0.x, acc[4]); acc[5] = fma2(a1, w0.y, acc[5]);
            acc[6] = fma2(a1, w1.x, acc[6]); acc[7] = fma2(a1, w1.y, acc[7]);
        }
    }

    #pragma unroll
    for (int r = 0; r < 2; ++r) {
        float* dst = g_MH + (R0 + ty * 2 + r) * 128 + tx * 8;
        ulonglong2 t;
        t.x = acc[r * 4 + 0]; t.y = acc[r * 4 + 1]; ((ulonglong2*)dst)[0] = t;
        t.x = acc[r * 4 + 2]; t.y = acc[r * 4 + 3]; ((ulonglong2*)dst)[1] = t;
    }
}

// ============================================================================
// Kernel 5: score2 = MH @ E^T + fused epilogue -> out.
// C-tile 64p x 128n, micro 4x8, f32x2. grid (8 n, 2 p, 64 b).
// ============================================================================
__global__ void __launch_bounds__(256, 2)
score_kernel(const float* __restrict__ Enodes,
             const float* __restrict__ cur_dist,
             const float* __restrict__ ninf,
             const float* __restrict__ noise,
             float* __restrict__ out) {
    const int b   = blockIdx.z;
    const int p0  = blockIdx.y * 64;
    const int n0  = blockIdx.x * 128;
    const int tid = threadIdx.x;
    const int tx  = tid & 15, ty = tid >> 4;

    __shared__ float Es[32][132];
    __shared__ float Ms[32][68];

    u64t acc[16];
    #pragma unroll
    for (int i = 0; i < 16; ++i) acc[i] = 0ull;

    for (int kc = 0; kc < 128; kc += 32) {
        __syncthreads();
        for (int l = tid; l < 4096; l += 256) {
            int n = l >> 5, k = l & 31;
            Es[k][n] = (n0 + n < 1000) ? Enodes[(b * 1000 + n0 + n) * 128 + kc + k] : 0.f;
        }
        for (int l = tid; l < 2048; l += 256) {
            int pp = l >> 5, k = l & 31;
            int p = p0 + pp;
            Ms[k][pp] = (p < 100) ? g_MH[(b * 100 + p) * 128 + kc + k] : 0.f;
        }
        __syncthreads();

        #pragma unroll 4
        for (int k = 0; k < 32; ++k) {
            float4 mv = *(const float4*)&Ms[k][ty * 4];
            u64t m0 = splat2(mv.x), m1 = splat2(mv.y), m2 = splat2(mv.z), m3 = splat2(mv.w);
            const ulonglong2* ep = (const ulonglong2*)&Es[k][tx * 8];
            ulonglong2 e0 = ep[0], e1 = ep[1];
            acc[0]  = fma2(m0, e0.x, acc[0]);  acc[1]  = fma2(m0, e0.y, acc[1]);
            acc[2]  = fma2(m0, e1.x, acc[2]);  acc[3]  = fma2(m0, e1.y, acc[3]);
            acc[4]  = fma2(m1, e0.x, acc[4]);  acc[5]  = fma2(m1, e0.y, acc[5]);
            acc[6]  = fma2(m1, e1.x, acc[6]);  acc[7]  = fma2(m1, e1.y, acc[7]);
            acc[8]  = fma2(m2, e0.x, acc[8]);  acc[9]  = fma2(m2, e0.y, acc[9]);
            acc[10] = fma2(m2, e1.x, acc[10]); acc[11] = fma2(m2, e1.y, acc[11]);
            acc[12] = fma2(m3, e0.x, acc[12]); acc[13] = fma2(m3, e0.y, acc[13]);
            acc[14] = fma2(m3, e1.x, acc[14]); acc[15] = fma2(m3, e1.y, acc[15]);
        }
    }

    const int nbase = n0 + tx * 8;      // 1000 % 8 == 0: block of 8 all-in or all-out
    if (nbase >= 1000) return;
    #pragma unroll
    for (int r = 0; r < 4; ++r) {
        int p = p0 + ty * 4 + r;
        if (p < 100) {
            int idx = (b * 100 + p) * 1000 + nbase;
            float sv[8];
            #pragma unroll
            for (int c = 0; c < 4; ++c) {
                float2 u = unpack2(acc[r * 4 + c]);
                sv[2 * c] = u.x; sv[2 * c + 1] = u.y;
            }
            float4 cd0 = *(const float4*)(cur_dist + idx);
            float4 cd1 = *(const float4*)(cur_dist + idx + 4);
            float4 nz0 = *(const float4*)(noise + idx);
            float4 nz1 = *(const float4*)(noise + idx + 4);
            float4 nf0 = *(const float4*)(ninf + idx);
            float4 nf1 = *(const float4*)(ninf + idx + 4);
            float cd[8] = {cd0.x, cd0.y, cd0.z, cd0.w, cd1.x, cd1.y, cd1.z, cd1.w};
            float nz[8] = {nz0.x, nz0.y, nz0.z, nz0.w, nz1.x, nz1.y, nz1.z, nz1.w};
            float nf[8] = {nf0.x, nf0.y, nf0.z, nf0.w, nf1.x, nf1.y, nf1.z, nf1.w};
            float res[8];
            #pragma unroll
            for (int j = 0; j < 8; ++j) {
                float heur = -__logf(fmaf(2.f, cd[j], 1e-6f));
                float s    = sv[j] * INV_SQRT_EMB + A_COEF * heur + B_COEF * nz[j];
                res[j]     = 10.f * tanhf(s) + nf[j];
            }
            *(float4*)(out + idx)     = make_float4(res[0], res[1], res[2], res[3]);
            *(float4*)(out + idx + 4) = make_float4(res[4], res[5], res[6], res[7]);
        }
    }
}

// ============================================================================
// Kernel 6: in-place row softmax over N=1000
// ============================================================================
__global__ void softmax_kernel(float* __restrict__ out) {
    const int row = blockIdx.x;
    const int tid = threadIdx.x;
    float* sp = out + row * 1000;

    float v[4];
    #pragma unroll
    for (int t = 0; t < 4; ++t) {
        int n = tid + t * 256;
        v[t] = (n < 1000) ? sp[n] : -INFINITY;
    }
    float m = fmaxf(fmaxf(v[0], v[1]), fmaxf(v[2], v[3]));
    #pragma unroll
    for (int o = 16; o; o >>= 1) m = fmaxf(m, __shfl_xor_sync(0xffffffffu, m, o));

    __shared__ float smax[8];
    __shared__ float ssum[8];
    if ((tid & 31) == 0) smax[tid >> 5] = m;
    __syncthreads();
    float M = smax[0];
    #pragma unroll
    for (int w = 1; w < 8; ++w) M = fmaxf(M, smax[w]);

    float e[4], lsum = 0.f;
    #pragma unroll
    for (int t = 0; t < 4; ++t) { e[t] = __expf(v[t] - M); lsum += e[t]; }
    #pragma unroll
    for (int o = 16; o; o >>= 1) lsum += __shfl_xor_sync(0xffffffffu, lsum, o);
    if ((tid & 31) == 0) ssum[tid >> 5] = lsum;
    __syncthreads();
    float S = 0.f;
    #pragma unroll
    for (int w = 0; w < 8; ++w) S += ssum[w];

    float inv = 1.f / S;
    #pragma unroll
    for (int t = 0; t < 4; ++t) {
        int n = tid + t * 256;
        if (n < 1000) sp[n] = e[t] * inv;
    }
}

// ============================================================================
extern "C" void kernel_launch(void* const* d_in, const int* in_sizes, int n_in,
                              void* d_out, int out_size) {
    const float* eln      = (const float*)d_in[0];
    const float* loadv    = (const float*)d_in[1];
    const float* timev    = (const float*)d_in[2];
    const float* cur_dist = (const float*)d_in[3];
    const float* ninf     = (const float*)d_in[4];
    const float* noise    = (const float*)d_in[5];
    const float* Enodes   = (const float*)d_in[6];
    const float* Wq       = (const float*)d_in[7];
    const float* Wk       = (const float*)d_in[8];
    const float* Wv       = (const float*)d_in[9];
    const float* Wc       = (const float*)d_in[10];
    const float* bc       = (const float*)d_in[11];
    float* out = (float*)d_out;

    kv_kernel<<<1000, 256>>>(Enodes, Wk, Wv);
    q_kernel<<<400, 128>>>(eln, loadv, timev, Wq);
    attn_kernel<<<512, 128>>>(ninf);
    mh_kernel<<<200, 256>>>(Wc, bc);
    score_kernel<<<dim3(8, 2, 64), 256>>>(Enodes, cur_dist, ninf, noise, out);
    softmax_kernel<<<6400, 256>>>(out);
}

// round 3
// speedup vs baseline: 1.6321x; 1.0993x over previous
#include <cuda_runtime.h>
#include <math.h>

#define Bc   64
#define Pc   100
#define Nc   1000
#define EMBc 128

// ---- scratch (__device__ globals; no allocation allowed) ----
__device__ __align__(16) float g_K[Bc * Nc * EMBc];
__device__ __align__(16) float g_V[Bc * Nc * EMBc];
__device__ __align__(16) float g_Q[Bc * Pc * EMBc];
__device__ __align__(16) float g_O[Bc * Pc * EMBc];
__device__ __align__(16) float g_MH[Bc * Pc * EMBc];
__device__ __align__(16) unsigned g_bits[Bc * Pc * 32];          // packed mask
__device__ __align__(16) float g_part[2 * 512 * Pc * 17];        // attn split partials

constexpr double X218   = 3.814697265625e-06;
constexpr float  A_COEF = (float)(1.0 / (1.0 + X218));
constexpr float  B_COEF = (float)(1.0 - 1.0 / (1.0 + X218));
constexpr float  INV_SQRT_EMB = 0.08838834764831845f;

// ---- packed fp32x2 helpers ----
typedef unsigned long long u64t;
__device__ __forceinline__ u64t fma2(u64t a, u64t b, u64t c) {
    u64t d; asm("fma.rn.f32x2 %0, %1, %2, %3;" : "=l"(d) : "l"(a), "l"(b), "l"(c)); return d;
}
__device__ __forceinline__ u64t mul2(u64t a, u64t b) {
    u64t d; asm("mul.rn.f32x2 %0, %1, %2;" : "=l"(d) : "l"(a), "l"(b)); return d;
}
__device__ __forceinline__ u64t add2(u64t a, u64t b) {
    u64t d; asm("add.rn.f32x2 %0, %1, %2;" : "=l"(d) : "l"(a), "l"(b)); return d;
}
__device__ __forceinline__ u64t splat2(float x) {
    u64t d; asm("mov.b64 %0, {%1, %1};" : "=l"(d) : "f"(x)); return d;
}
__device__ __forceinline__ float2 unpack2(u64t v) {
    float2 r; asm("mov.b64 {%0, %1}, %2;" : "=f"(r.x), "=f"(r.y) : "l"(v)); return r;
}

// ---- cp.async helpers ----
__device__ __forceinline__ void cp16(void* dst, const void* src) {
    unsigned d = (unsigned)__cvta_generic_to_shared(dst);
    asm volatile("cp.async.cg.shared.global [%0], [%1], 16;" :: "r"(d), "l"(src));
}
#define CP_COMMIT() asm volatile("cp.async.commit_group;" ::: "memory")

// ============================================================================
// Kernel 0: pack ninf mask into bits (1 = masked).  value set is {0, -1e9}.
// ============================================================================
__global__ void bits_kernel(const float* __restrict__ ninf) {
    const int w = blockIdx.x * 8 + (threadIdx.x >> 5);   // word id, 256 thr = 8 words
    if (w >= Bc * Pc * 32) return;
    const int lane = threadIdx.x & 31;
    const int row = w >> 5, word = w & 31;
    const int n = word * 32 + lane;
    float v = -1.f;
    if (n < 1000) v = ninf[row * 1000 + n];
    unsigned m = __ballot_sync(0xffffffffu, v < -0.5f);
    if (lane == 0) g_bits[w] = m;
}

// ============================================================================
// Kernel 1: K = E @ Wk, V = E @ Wv. 64x128 tile, f32x2, cp.async double buffer.
// ============================================================================
__global__ void __launch_bounds__(256, 2)
kv_kernel(const float* __restrict__ E,
          const float* __restrict__ Wk,
          const float* __restrict__ Wv) {
    __shared__ __align__(16) float As[2][64][20];
    __shared__ __align__(16) float Wks[2][16][128];
    __shared__ __align__(16) float Wvs[2][16][128];
    const int tid = threadIdx.x;
    const int R0  = blockIdx.x * 64;
    const int tx  = tid & 15;
    const int ty  = tid >> 4;
    const int arow = tid >> 2, akq = (tid & 3) * 4;

    u64t accK[16], accV[16];
    #pragma unroll
    for (int i = 0; i < 16; ++i) { accK[i] = 0ull; accV[i] = 0ull; }

    // stage chunk 0
    {
        cp16(&As[0][arow][akq], E + (R0 + arow) * 128 + akq);
        #pragma unroll
        for (int i = 0; i < 2; ++i) {
            int l = tid + i * 256;
            int kr = l >> 5, c4 = (l & 31) * 4;
            cp16(&Wks[0][kr][c4], Wk + kr * 128 + c4);
            cp16(&Wvs[0][kr][c4], Wv + kr * 128 + c4);
        }
        CP_COMMIT();
    }

    for (int c = 0; c < 8; ++c) {
        const int s = c & 1;
        if (c + 1 < 8) {
            const int ns = 1 - s, kc = (c + 1) * 16;
            cp16(&As[ns][arow][akq], E + (R0 + arow) * 128 + kc + akq);
            #pragma unroll
            for (int i = 0; i < 2; ++i) {
                int l = tid + i * 256;
                int kr = l >> 5, c4 = (l & 31) * 4;
                cp16(&Wks[ns][kr][c4], Wk + (kc + kr) * 128 + c4);
                cp16(&Wvs[ns][kr][c4], Wv + (kc + kr) * 128 + c4);
            }
            CP_COMMIT();
            asm volatile("cp.async.wait_group 1;" ::: "memory");
        } else {
            asm volatile("cp.async.wait_group 0;" ::: "memory");
        }
        __syncthreads();

        #pragma unroll 4
        for (int k = 0; k < 16; ++k) {
            float a0f = As[s][ty * 4 + 0][k];
            float a1f = As[s][ty * 4 + 1][k];
            float a2f = As[s][ty * 4 + 2][k];
            float a3f = As[s][ty * 4 + 3][k];
            u64t a0 = splat2(a0f), a1 = splat2(a1f), a2 = splat2(a2f), a3 = splat2(a3f);
            const ulonglong2* wkp = (const ulonglong2*)&Wks[s][k][tx * 8];
            ulonglong2 wk0 = wkp[0], wk1 = wkp[1];
            const ulonglong2* wvp = (const ulonglong2*)&Wvs[s][k][tx * 8];
            ulonglong2 wv0 = wvp[0], wv1 = wvp[1];

            accK[0]  = fma2(a0, wk0.x, accK[0]);  accK[1]  = fma2(a0, wk0.y, accK[1]);
            accK[2]  = fma2(a0, wk1.x, accK[2]);  accK[3]  = fma2(a0, wk1.y, accK[3]);
            accK[4]  = fma2(a1, wk0.x, accK[4]);  accK[5]  = fma2(a1, wk0.y, accK[5]);
            accK[6]  = fma2(a1, wk1.x, accK[6]);  accK[7]  = fma2(a1, wk1.y, accK[7]);
            accK[8]  = fma2(a2, wk0.x, accK[8]);  accK[9]  = fma2(a2, wk0.y, accK[9]);
            accK[10] = fma2(a2, wk1.x, accK[10]); accK[11] = fma2(a2, wk1.y, accK[11]);
            accK[12] = fma2(a3, wk0.x, accK[12]); accK[13] = fma2(a3, wk0.y, accK[13]);
            accK[14] = fma2(a3, wk1.x, accK[14]); accK[15] = fma2(a3, wk1.y, accK[15]);

            accV[0]  = fma2(a0, wv0.x, accV[0]);  accV[1]  = fma2(a0, wv0.y, accV[1]);
            accV[2]  = fma2(a0, wv1.x, accV[2]);  accV[3]  = fma2(a0, wv1.y, accV[3]);
            accV[4]  = fma2(a1, wv0.x, accV[4]);  accV[5]  = fma2(a1, wv0.y, accV[5]);
            accV[6]  = fma2(a1, wv1.x, accV[6]);  accV[7]  = fma2(a1, wv1.y, accV[7]);
            accV[8]  = fma2(a2, wv0.x, accV[8]);  accV[9]  = fma2(a2, wv0.y, accV[9]);
            accV[10] = fma2(a2, wv1.x, accV[10]); accV[11] = fma2(a2, wv1.y, accV[11]);
            accV[12] = fma2(a3, wv0.x, accV[12]); accV[13] = fma2(a3, wv0.y, accV[13]);
            accV[14] = fma2(a3, wv1.x, accV[14]); accV[15] = fma2(a3, wv1.y, accV[15]);
        }
        __syncthreads();
    }

    #pragma unroll
    for (int r = 0; r < 4; ++r) {
        float* dk = g_K + (R0 + ty * 4 + r) * 128 + tx * 8;
        float* dv = g_V + (R0 + ty * 4 + r) * 128 + tx * 8;
        ulonglong2 t;
        t.x = accK[r * 4 + 0]; t.y = accK[r * 4 + 1]; ((ulonglong2*)dk)[0] = t;
        t.x = accK[r * 4 + 2]; t.y = accK[r * 4 + 3]; ((ulonglong2*)dk)[1] = t;
        t.x = accV[r * 4 + 0]; t.y = accV[r * 4 + 1]; ((ulonglong2*)dv)[0] = t;
        t.x = accV[r * 4 + 2]; t.y = accV[r * 4 + 3]; ((ulonglong2*)dv)[1] = t;
    }
}

// ============================================================================
// Kernel 2: Q = concat(eln, load, time) @ Wq
// ============================================================================
__global__ void q_kernel(const float* __restrict__ eln,
                         const float* __restrict__ loadv,
                         const float* __restrict__ timev,
                         const float* __restrict__ Wq) {
    __shared__ __align__(16) float sA[130][16];
    const int r0  = blockIdx.x * 16;
    const int tid = threadIdx.x;

    for (int l = tid; l < 130 * 16; l += 128) {
        int k = l >> 4, r = l & 15;
        int g = r0 + r;
        float v;
        if (k < 128)       v = eln[g * 128 + k];
        else if (k == 128) v = loadv[g];
        else               v = timev[g];
        sA[k][r] = v;
    }
    __syncthreads();

    const int c = tid;
    float acc[16];
    #pragma unroll
    for (int i = 0; i < 16; ++i) acc[i] = 0.f;

    for (int k = 0; k < 130; ++k) {
        float w = Wq[k * 128 + c];
        float a[16];
        const float4* ap = (const float4*)sA[k];
        ((float4*)a)[0] = ap[0]; ((float4*)a)[1] = ap[1];
        ((float4*)a)[2] = ap[2]; ((float4*)a)[3] = ap[3];
        #pragma unroll
        for (int i = 0; i < 16; ++i) acc[i] = fmaf(a[i], w, acc[i]);
    }
    #pragma unroll
    for (int i = 0; i < 16; ++i) g_Q[(r0 + i) * 128 + c] = acc[i];
}

// ============================================================================
// Kernel 3: attention, split-k over n (2 splits of 500). block=(bh, split).
// Mask applied via bitmask select (exact: exp(-1e9)==0 in fp32).
// ============================================================================
__global__ void __launch_bounds__(128, 8)
attn_kernel() {
    const int bh    = blockIdx.x;            // b*8+h
    const int split = blockIdx.y;
    const int b     = bh >> 3;
    const int h     = bh & 7;
    const int tid   = threadIdx.x;
    const int nbase = split * 500;

    __shared__ __align__(16) float Kt[100][16];
    __shared__ __align__(16) float Vt[100][16];
    __shared__ unsigned Sb[100][33];

    // stage full-row bitmask for this b (100 rows x 32 words)
    for (int l = tid; l < 100 * 32; l += 128)
        Sb[l >> 5][l & 31] = g_bits[(b * 100 + (l >> 5)) * 32 + (l & 31)];

    u64t q2[8];
    #pragma unroll
    for (int i = 0; i < 8; ++i) q2[i] = 0ull;
    if (tid < 100) {
        const ulonglong2* qp = (const ulonglong2*)(g_Q + (b * 100 + tid) * 128 + h * 16);
        u64t qs = splat2(0.25f);
        #pragma unroll
        for (int i = 0; i < 4; ++i) {
            ulonglong2 t = qp[i];
            q2[2 * i]     = mul2(t.x, qs);
            q2[2 * i + 1] = mul2(t.y, qs);
        }
    }

    u64t acc2[8];
    #pragma unroll
    for (int i = 0; i < 8; ++i) acc2[i] = 0ull;
    float lsum = 0.f;

    const float* Kbase = g_K + b * 1000 * 128 + h * 16;
    const float* Vbase = g_V + b * 1000 * 128 + h * 16;

    for (int n0 = 0; n0 < 500; n0 += 100) {
        __syncthreads();
        for (int l = tid; l < 100 * 4; l += 128) {
            int n = l >> 2, qd = l & 3;
            ((float4*)Kt[n])[qd] = *(const float4*)(Kbase + (nbase + n0 + n) * 128 + qd * 4);
            ((float4*)Vt[n])[qd] = *(const float4*)(Vbase + (nbase + n0 + n) * 128 + qd * 4);
        }
        __syncthreads();

        if (tid < 100) {
            #pragma unroll 4
            for (int j = 0; j < 100; ++j) {
                const ulonglong2* kp = (const ulonglong2*)Kt[j];
                ulonglong2 ka = kp[0], kb = kp[1], kc2 = kp[2], kd = kp[3];
                u64t d0 = mul2(q2[0], ka.x);
                u64t d1 = mul2(q2[1], ka.y);
                d0 = fma2(q2[2], kb.x,  d0);
                d1 = fma2(q2[3], kb.y,  d1);
                d0 = fma2(q2[4], kc2.x, d0);
                d1 = fma2(q2[5], kc2.y, d1);
                d0 = fma2(q2[6], kd.x,  d0);
                d1 = fma2(q2[7], kd.y,  d1);
                float2 sv = unpack2(add2(d0, d1));
                const int n = nbase + n0 + j;
                const unsigned wd = Sb[tid][n >> 5];
                float e = __expf(sv.x + sv.y);
                if ((wd >> (n & 31)) & 1u) e = 0.f;
                lsum += e;
                u64t e2 = splat2(e);
                const ulonglong2* vp = (const ulonglong2*)Vt[j];
                ulonglong2 va = vp[0], vb = vp[1], vc = vp[2], vd = vp[3];
                acc2[0] = fma2(e2, va.x, acc2[0]); acc2[1] = fma2(e2, va.y, acc2[1]);
                acc2[2] = fma2(e2, vb.x, acc2[2]); acc2[3] = fma2(e2, vb.y, acc2[3]);
                acc2[4] = fma2(e2, vc.x, acc2[4]); acc2[5] = fma2(e2, vc.y, acc2[5]);
                acc2[6] = fma2(e2, vd.x, acc2[6]); acc2[7] = fma2(e2, vd.y, acc2[7]);
            }
        }
    }

    if (tid < 100) {
        float* pp = g_part + ((split * 512 + bh) * 100 + tid) * 17;
        #pragma unroll
        for (int i = 0; i < 8; ++i) {
            float2 u = unpack2(acc2[i]);
            pp[2 * i] = u.x; pp[2 * i + 1] = u.y;
        }
        pp[16] = lsum;
    }
}

// ============================================================================
// Kernel 3b: combine attn splits -> g_O
// ============================================================================
__global__ void attn_combine() {
    const int u = blockIdx.x * 256 + threadIdx.x;
    if (u >= 512 * 100) return;
    const int bh = u / 100, p = u % 100;
    const float* p0 = g_part + ((0 * 512 + bh) * 100 + p) * 17;
    const float* p1 = g_part + ((1 * 512 + bh) * 100 + p) * 17;
    const float inv = 1.f / (p0[16] + p1[16]);
    const int b = bh >> 3, h = bh & 7;
    float* op = g_O + (b * 100 + p) * 128 + h * 16;
    #pragma unroll
    for (int i = 0; i < 16; ++i) op[i] = (p0[i] + p1[i]) * inv;
}

// ============================================================================
// Kernel 4: MH = O @ Wc + bc. 16 rows/block, W streamed from L2, f32x2.
// ============================================================================
__global__ void __launch_bounds__(256)
mh_kernel(const float* __restrict__ Wc, const float* __restrict__ bc) {
    __shared__ float As[128][20];
    const int tid = threadIdx.x;
    const int R0  = blockIdx.x * 16;
    const int tx  = tid & 63;          // col pair 2tx..2tx+1
    const int ty  = tid >> 6;          // rows ty*4..+3

    for (int l = tid; l < 2048; l += 256) {
        int row = l >> 7, col = l & 127;
        As[col][row] = g_O[(R0 + row) * 128 + col];
    }
    __syncthreads();

    u64t acc[4];
    {
        float2 bb = *(const float2*)(bc + tx * 2);
        u64t bb2; asm("mov.b64 %0, {%1, %2};" : "=l"(bb2) : "f"(bb.x), "f"(bb.y));
        acc[0] = bb2; acc[1] = bb2; acc[2] = bb2; acc[3] = bb2;
    }

    #pragma unroll 8
    for (int k = 0; k < 128; ++k) {
        u64t w = *(const u64t*)(Wc + k * 128 + tx * 2);
        float4 a = *(const float4*)&As[k][ty * 4];
        acc[0] = fma2(splat2(a.x), w, acc[0]);
        acc[1] = fma2(splat2(a.y), w, acc[1]);
        acc[2] = fma2(splat2(a.z), w, acc[2]);
        acc[3] = fma2(splat2(a.w), w, acc[3]);
    }

    #pragma unroll
    for (int r = 0; r < 4; ++r)
        *(u64t*)(g_MH + (R0 + ty * 4 + r) * 128 + tx * 2) = acc[r];
}

// ============================================================================
// Kernel 5: score = MH @ E^T + fused heuristic/noise/tanh epilogue (no mask).
// ============================================================================
__global__ void __launch_bounds__(256, 2)
score_kernel(const float* __restrict__ Enodes,
             const float* __restrict__ cur_dist,
             const float* __restrict__ noise,
             float* __restrict__ out) {
    const int b   = blockIdx.z;
    const int p0  = blockIdx.y * 64;
    const int n0  = blockIdx.x * 128;
    const int tid = threadIdx.x;
    const int tx  = tid & 15, ty = tid >> 4;

    __shared__ float Es[32][132];
    __shared__ float Ms[32][68];

    u64t acc[16];
    #pragma unroll
    for (int i = 0; i < 16; ++i) acc[i] = 0ull;

    for (int kc = 0; kc < 128; kc += 32) {
        __syncthreads();
        for (int l = tid; l < 4096; l += 256) {
            int n = l >> 5, k = l & 31;
            Es[k][n] = (n0 + n < 1000) ? Enodes[(b * 1000 + n0 + n) * 128 + kc + k] : 0.f;
        }
        for (int l = tid; l < 2048; l += 256) {
            int pp = l >> 5, k = l & 31;
            int p = p0 + pp;
            Ms[k][pp] = (p < 100) ? g_MH[(b * 100 + p) * 128 + kc + k] : 0.f;
        }
        __syncthreads();

        #pragma unroll 4
        for (int k = 0; k < 32; ++k) {
            float4 mv = *(const float4*)&Ms[k][ty * 4];
            u64t m0 = splat2(mv.x), m1 = splat2(mv.y), m2 = splat2(mv.z), m3 = splat2(mv.w);
            const ulonglong2* ep = (const ulonglong2*)&Es[k][tx * 8];
            ulonglong2 e0 = ep[0], e1 = ep[1];
            acc[0]  = fma2(m0, e0.x, acc[0]);  acc[1]  = fma2(m0, e0.y, acc[1]);
            acc[2]  = fma2(m0, e1.x, acc[2]);  acc[3]  = fma2(m0, e1.y, acc[3]);
            acc[4]  = fma2(m1, e0.x, acc[4]);  acc[5]  = fma2(m1, e0.y, acc[5]);
            acc[6]  = fma2(m1, e1.x, acc[6]);  acc[7]  = fma2(m1, e1.y, acc[7]);
            acc[8]  = fma2(m2, e0.x, acc[8]);  acc[9]  = fma2(m2, e0.y, acc[9]);
            acc[10] = fma2(m2, e1.x, acc[10]); acc[11] = fma2(m2, e1.y, acc[11]);
            acc[12] = fma2(m3, e0.x, acc[12]); acc[13] = fma2(m3, e0.y, acc[13]);
            acc[14] = fma2(m3, e1.x, acc[14]); acc[15] = fma2(m3, e1.y, acc[15]);
        }
    }

    const int nbase = n0 + tx * 8;
    if (nbase >= 1000) return;
    #pragma unroll
    for (int r = 0; r < 4; ++r) {
        int p = p0 + ty * 4 + r;
        if (p < 100) {
            int idx = (b * 100 + p) * 1000 + nbase;
            float sv[8];
            #pragma unroll
            for (int c = 0; c < 4; ++c) {
                float2 u = unpack2(acc[r * 4 + c]);
                sv[2 * c] = u.x; sv[2 * c + 1] = u.y;
            }
            float4 cd0 = *(const float4*)(cur_dist + idx);
            float4 cd1 = *(const float4*)(cur_dist + idx + 4);
            float4 nz0 = *(const float4*)(noise + idx);
            float4 nz1 = *(const float4*)(noise + idx + 4);
            float cd[8] = {cd0.x, cd0.y, cd0.z, cd0.w, cd1.x, cd1.y, cd1.z, cd1.w};
            float nz[8] = {nz0.x, nz0.y, nz0.z, nz0.w, nz1.x, nz1.y, nz1.z, nz1.w};
            float res[8];
            #pragma unroll
            for (int j = 0; j < 8; ++j) {
                float heur = -__logf(fmaf(2.f, cd[j], 1e-6f));
                float s    = sv[j] * INV_SQRT_EMB + A_COEF * heur + B_COEF * nz[j];
                res[j]     = 10.f * tanhf(s);
            }
            *(float4*)(out + idx)     = make_float4(res[0], res[1], res[2], res[3]);
            *(float4*)(out + idx + 4) = make_float4(res[4], res[5], res[6], res[7]);
        }
    }
}

// ============================================================================
// Kernel 6: masked in-place row softmax over N=1000 (mask from bits)
// ============================================================================
__global__ void softmax_kernel(float* __restrict__ out) {
    const int row = blockIdx.x;
    const int tid = threadIdx.x;
    float* sp = out + row * 1000;

    __shared__ unsigned sbw[32];
    if (tid < 32) sbw[tid] = g_bits[row * 32 + tid];
    __syncthreads();

    float v[4];
    #pragma unroll
    for (int t = 0; t < 4; ++t) {
        int n = tid + t * 256;
        float x = -1e30f;
        if (n < 1000) {
            x = sp[n];
            if ((sbw[n >> 5] >> (n & 31)) & 1u) x = -1e30f;
        }
        v[t] = x;
    }
    float m = fmaxf(fmaxf(v[0], v[1]), fmaxf(v[2], v[3]));
    #pragma unroll
    for (int o = 16; o; o >>= 1) m = fmaxf(m, __shfl_xor_sync(0xffffffffu, m, o));

    __shared__ float smax[8];
    __shared__ float ssum[8];
    if ((tid & 31) == 0) smax[tid >> 5] = m;
    __syncthreads();
    float M = smax[0];
    #pragma unroll
    for (int w = 1; w < 8; ++w) M = fmaxf(M, smax[w]);

    float e[4], lsum = 0.f;
    #pragma unroll
    for (int t = 0; t < 4; ++t) { e[t] = __expf(v[t] - M); lsum += e[t]; }
    #pragma unroll
    for (int o = 16; o; o >>= 1) lsum += __shfl_xor_sync(0xffffffffu, lsum, o);
    if ((tid & 31) == 0) ssum[tid >> 5] = lsum;
    __syncthreads();
    float S = 0.f;
    #pragma unroll
    for (int w = 0; w < 8; ++w) S += ssum[w];

    float inv = 1.f / S;
    #pragma unroll
    for (int t = 0; t < 4; ++t) {
        int n = tid + t * 256;
        if (n < 1000) sp[n] = e[t] * inv;
    }
}

// ============================================================================
extern "C" void kernel_launch(void* const* d_in, const int* in_sizes, int n_in,
                              void* d_out, int out_size) {
    const float* eln      = (const float*)d_in[0];
    const float* loadv    = (const float*)d_in[1];
    const float* timev    = (const float*)d_in[2];
    const float* cur_dist = (const float*)d_in[3];
    const float* ninf     = (const float*)d_in[4];
    const float* noise    = (const float*)d_in[5];
    const float* Enodes   = (const float*)d_in[6];
    const float* Wq       = (const float*)d_in[7];
    const float* Wk       = (const float*)d_in[8];
    const float* Wv       = (const float*)d_in[9];
    const float* Wc       = (const float*)d_in[10];
    const float* bc       = (const float*)d_in[11];
    float* out = (float*)d_out;

    bits_kernel<<<25600, 256>>>(ninf);
    kv_kernel<<<1000, 256>>>(Enodes, Wk, Wv);
    q_kernel<<<400, 128>>>(eln, loadv, timev, Wq);
    attn_kernel<<<dim3(512, 2), 128>>>();
    attn_combine<<<200, 256>>>();
    mh_kernel<<<400, 256>>>(Wc, bc);
    score_kernel<<<dim3(8, 2, 64), 256>>>(Enodes, cur_dist, noise, out);
    softmax_kernel<<<6400, 256>>>(out);
}

// round 4
// speedup vs baseline: 1.7077x; 1.0463x over previous
#include <cuda_runtime.h>
#include <math.h>

#define Bc   64
#define Pc   100
#define Nc   1000
#define EMBc 128

// ---- scratch (__device__ globals; no allocation allowed) ----
__device__ __align__(16) float g_K[Bc * Nc * EMBc];
__device__ __align__(16) float g_V[Bc * Nc * EMBc];
__device__ __align__(16) float g_Q[Bc * Pc * EMBc];
__device__ __align__(16) float g_O[Bc * Pc * EMBc];
__device__ __align__(16) float g_MH[Bc * Pc * EMBc];
__device__ __align__(16) unsigned g_bits[Bc * Pc * 32];          // packed mask
__device__ __align__(16) float g_part[4 * 512 * Pc * 17];        // attn split partials

constexpr double X218   = 3.814697265625e-06;
constexpr float  A_COEF = (float)(1.0 / (1.0 + X218));
constexpr float  B_COEF = (float)(1.0 - 1.0 / (1.0 + X218));
constexpr float  INV_SQRT_EMB = 0.08838834764831845f;
constexpr float  LOG2E = 1.44269504088896340736f;

// ---- packed fp32x2 helpers ----
typedef unsigned long long u64t;
__device__ __forceinline__ u64t fma2(u64t a, u64t b, u64t c) {
    u64t d; asm("fma.rn.f32x2 %0, %1, %2, %3;" : "=l"(d) : "l"(a), "l"(b), "l"(c)); return d;
}
__device__ __forceinline__ u64t mul2(u64t a, u64t b) {
    u64t d; asm("mul.rn.f32x2 %0, %1, %2;" : "=l"(d) : "l"(a), "l"(b)); return d;
}
__device__ __forceinline__ u64t add2(u64t a, u64t b) {
    u64t d; asm("add.rn.f32x2 %0, %1, %2;" : "=l"(d) : "l"(a), "l"(b)); return d;
}
__device__ __forceinline__ u64t splat2(float x) {
    u64t d; asm("mov.b64 %0, {%1, %1};" : "=l"(d) : "f"(x)); return d;
}
__device__ __forceinline__ float2 unpack2(u64t v) {
    float2 r; asm("mov.b64 {%0, %1}, %2;" : "=f"(r.x), "=f"(r.y) : "l"(v)); return r;
}
__device__ __forceinline__ float ex2f(float x) {
    float r; asm("ex2.approx.f32 %0, %1;" : "=f"(r) : "f"(x)); return r;
}

// ---- cp.async helpers ----
__device__ __forceinline__ void cp16(void* dst, const void* src) {
    unsigned d = (unsigned)__cvta_generic_to_shared(dst);
    asm volatile("cp.async.cg.shared.global [%0], [%1], 16;" :: "r"(d), "l"(src));
}
#define CP_COMMIT() asm volatile("cp.async.commit_group;" ::: "memory")

// ============================================================================
// Kernel 0: pack ninf mask into bits (1 = masked).
// ============================================================================
__global__ void bits_kernel(const float* __restrict__ ninf) {
    const int w = blockIdx.x * 8 + (threadIdx.x >> 5);
    if (w >= Bc * Pc * 32) return;
    const int lane = threadIdx.x & 31;
    const int row = w >> 5, word = w & 31;
    const int n = word * 32 + lane;
    float v = -1.f;
    if (n < 1000) v = ninf[row * 1000 + n];
    unsigned m = __ballot_sync(0xffffffffu, v < -0.5f);
    if (lane == 0) g_bits[w] = m;
}

// ============================================================================
// Kernel 1: K = E @ Wk, V = E @ Wv. 64x128 tile, f32x2, cp.async double buffer.
// ============================================================================
__global__ void __launch_bounds__(256, 2)
kv_kernel(const float* __restrict__ E,
          const float* __restrict__ Wk,
          const float* __restrict__ Wv) {
    __shared__ __align__(16) float As[2][64][20];
    __shared__ __align__(16) float Wks[2][16][128];
    __shared__ __align__(16) float Wvs[2][16][128];
    const int tid = threadIdx.x;
    const int R0  = blockIdx.x * 64;
    const int tx  = tid & 15;
    const int ty  = tid >> 4;
    const int arow = tid >> 2, akq = (tid & 3) * 4;

    u64t accK[16], accV[16];
    #pragma unroll
    for (int i = 0; i < 16; ++i) { accK[i] = 0ull; accV[i] = 0ull; }

    {
        cp16(&As[0][arow][akq], E + (R0 + arow) * 128 + akq);
        #pragma unroll
        for (int i = 0; i < 2; ++i) {
            int l = tid + i * 256;
            int kr = l >> 5, c4 = (l & 31) * 4;
            cp16(&Wks[0][kr][c4], Wk + kr * 128 + c4);
            cp16(&Wvs[0][kr][c4], Wv + kr * 128 + c4);
        }
        CP_COMMIT();
    }

    for (int c = 0; c < 8; ++c) {
        const int s = c & 1;
        if (c + 1 < 8) {
            const int ns = 1 - s, kc = (c + 1) * 16;
            cp16(&As[ns][arow][akq], E + (R0 + arow) * 128 + kc + akq);
            #pragma unroll
            for (int i = 0; i < 2; ++i) {
                int l = tid + i * 256;
                int kr = l >> 5, c4 = (l & 31) * 4;
                cp16(&Wks[ns][kr][c4], Wk + (kc + kr) * 128 + c4);
                cp16(&Wvs[ns][kr][c4], Wv + (kc + kr) * 128 + c4);
            }
            CP_COMMIT();
            asm volatile("cp.async.wait_group 1;" ::: "memory");
        } else {
            asm volatile("cp.async.wait_group 0;" ::: "memory");
        }
        __syncthreads();

        #pragma unroll 4
        for (int k = 0; k < 16; ++k) {
            float a0f = As[s][ty * 4 + 0][k];
            float a1f = As[s][ty * 4 + 1][k];
            float a2f = As[s][ty * 4 + 2][k];
            float a3f = As[s][ty * 4 + 3][k];
            u64t a0 = splat2(a0f), a1 = splat2(a1f), a2 = splat2(a2f), a3 = splat2(a3f);
            const ulonglong2* wkp = (const ulonglong2*)&Wks[s][k][tx * 8];
            ulonglong2 wk0 = wkp[0], wk1 = wkp[1];
            const ulonglong2* wvp = (const ulonglong2*)&Wvs[s][k][tx * 8];
            ulonglong2 wv0 = wvp[0], wv1 = wvp[1];

            accK[0]  = fma2(a0, wk0.x, accK[0]);  accK[1]  = fma2(a0, wk0.y, accK[1]);
            accK[2]  = fma2(a0, wk1.x, accK[2]);  accK[3]  = fma2(a0, wk1.y, accK[3]);
            accK[4]  = fma2(a1, wk0.x, accK[4]);  accK[5]  = fma2(a1, wk0.y, accK[5]);
            accK[6]  = fma2(a1, wk1.x, accK[6]);  accK[7]  = fma2(a1, wk1.y, accK[7]);
            accK[8]  = fma2(a2, wk0.x, accK[8]);  accK[9]  = fma2(a2, wk0.y, accK[9]);
            accK[10] = fma2(a2, wk1.x, accK[10]); accK[11] = fma2(a2, wk1.y, accK[11]);
            accK[12] = fma2(a3, wk0.x, accK[12]); accK[13] = fma2(a3, wk0.y, accK[13]);
            accK[14] = fma2(a3, wk1.x, accK[14]); accK[15] = fma2(a3, wk1.y, accK[15]);

            accV[0]  = fma2(a0, wv0.x, accV[0]);  accV[1]  = fma2(a0, wv0.y, accV[1]);
            accV[2]  = fma2(a0, wv1.x, accV[2]);  accV[3]  = fma2(a0, wv1.y, accV[3]);
            accV[4]  = fma2(a1, wv0.x, accV[4]);  accV[5]  = fma2(a1, wv0.y, accV[5]);
            accV[6]  = fma2(a1, wv1.x, accV[6]);  accV[7]  = fma2(a1, wv1.y, accV[7]);
            accV[8]  = fma2(a2, wv0.x, accV[8]);  accV[9]  = fma2(a2, wv0.y, accV[9]);
            accV[10] = fma2(a2, wv1.x, accV[10]); accV[11] = fma2(a2, wv1.y, accV[11]);
            accV[12] = fma2(a3, wv0.x, accV[12]); accV[13] = fma2(a3, wv0.y, accV[13]);
            accV[14] = fma2(a3, wv1.x, accV[14]); accV[15] = fma2(a3, wv1.y, accV[15]);
        }
        __syncthreads();
    }

    #pragma unroll
    for (int r = 0; r < 4; ++r) {
        float* dk = g_K + (R0 + ty * 4 + r) * 128 + tx * 8;
        float* dv = g_V + (R0 + ty * 4 + r) * 128 + tx * 8;
        ulonglong2 t;
        t.x = accK[r * 4 + 0]; t.y = accK[r * 4 + 1]; ((ulonglong2*)dk)[0] = t;
        t.x = accK[r * 4 + 2]; t.y = accK[r * 4 + 3]; ((ulonglong2*)dk)[1] = t;
        t.x = accV[r * 4 + 0]; t.y = accV[r * 4 + 1]; ((ulonglong2*)dv)[0] = t;
        t.x = accV[r * 4 + 2]; t.y = accV[r * 4 + 3]; ((ulonglong2*)dv)[1] = t;
    }
}

// ============================================================================
// Kernel 2: Q = concat(eln, load, time) @ Wq
// ============================================================================
__global__ void q_kernel(const float* __restrict__ eln,
                         const float* __restrict__ loadv,
                         const float* __restrict__ timev,
                         const float* __restrict__ Wq) {
    __shared__ __align__(16) float sA[130][16];
    const int r0  = blockIdx.x * 16;
    const int tid = threadIdx.x;

    for (int l = tid; l < 130 * 16; l += 128) {
        int k = l >> 4, r = l & 15;
        int g = r0 + r;
        float v;
        if (k < 128)       v = eln[g * 128 + k];
        else if (k == 128) v = loadv[g];
        else               v = timev[g];
        sA[k][r] = v;
    }
    __syncthreads();

    const int c = tid;
    float acc[16];
    #pragma unroll
    for (int i = 0; i < 16; ++i) acc[i] = 0.f;

    for (int k = 0; k < 130; ++k) {
        float w = Wq[k * 128 + c];
        float a[16];
        const float4* ap = (const float4*)sA[k];
        ((float4*)a)[0] = ap[0]; ((float4*)a)[1] = ap[1];
        ((float4*)a)[2] = ap[2]; ((float4*)a)[3] = ap[3];
        #pragma unroll
        for (int i = 0; i < 16; ++i) acc[i] = fmaf(a[i], w, acc[i]);
    }
    #pragma unroll
    for (int i = 0; i < 16; ++i) g_Q[(r0 + i) * 128 + c] = acc[i];
}

// ============================================================================
// Kernel 3: attention. block = (bh, split of 256 n). 64 threads (2 warps);
// thread t<50 handles queries p=t and p=t+50 -> K/V broadcast LDS halved.
// Mask bits read per-32j straight from L2 into registers.
// exp folded: q prescaled by 0.25*log2e, ex2.approx (== __expf path).
// ============================================================================
__global__ void __launch_bounds__(64, 7)
attn_kernel() {
    const int bh    = blockIdx.x;
    const int split = blockIdx.y;
    const int b     = bh >> 3;
    const int h     = bh & 7;
    const int tid   = threadIdx.x;
    const int nbeg  = split * 256;
    const int nend  = (nbeg + 256 < 1000) ? (nbeg + 256) : 1000;

    __shared__ __align__(16) float Kt[2][128][16];
    __shared__ __align__(16) float Vt[2][128][16];

    const float* Kbase = g_K + b * 1000 * 128 + h * 16;
    const float* Vbase = g_V + b * 1000 * 128 + h * 16;

    // stage tile 0
    {
        int cnt0 = nend - nbeg; if (cnt0 > 128) cnt0 = 128;
        for (int l = tid; l < cnt0 * 4; l += 64) {
            int j = l >> 2, qd = (l & 3) * 4;
            cp16(&Kt[0][j][qd], Kbase + (nbeg + j) * 128 + qd);
            cp16(&Vt[0][j][qd], Vbase + (nbeg + j) * 128 + qd);
        }
        CP_COMMIT();
    }

    u64t q0[8], q1[8], a0[8], a1[8];
    #pragma unroll
    for (int i = 0; i < 8; ++i) { q0[i] = 0ull; q1[i] = 0ull; a0[i] = 0ull; a1[i] = 0ull; }
    float ls0 = 0.f, ls1 = 0.f;
    const unsigned* bits0 = g_bits;
    const unsigned* bits1 = g_bits;

    if (tid < 50) {
        const ulonglong2* qp0 = (const ulonglong2*)(g_Q + (b * 100 + tid) * 128 + h * 16);
        const ulonglong2* qp1 = (const ulonglong2*)(g_Q + (b * 100 + tid + 50) * 128 + h * 16);
        u64t qs = splat2(0.25f * LOG2E);
        #pragma unroll
        for (int i = 0; i < 4; ++i) {
            ulonglong2 t0 = qp0[i], t1 = qp1[i];
            q0[2 * i]     = mul2(t0.x, qs);
            q0[2 * i + 1] = mul2(t0.y, qs);
            q1[2 * i]     = mul2(t1.x, qs);
            q1[2 * i + 1] = mul2(t1.y, qs);
        }
        bits0 = g_bits + (b * 100 + tid) * 32;
        bits1 = g_bits + (b * 100 + tid + 50) * 32;
    }

    const int ntiles = (nend - nbeg + 127) >> 7;
    for (int t = 0; t < ntiles; ++t) {
        const int s    = t & 1;
        const int base = nbeg + t * 128;
        int cnt = nend - base; if (cnt > 128) cnt = 128;

        if (t + 1 < ntiles) {
            const int ns = 1 - s, nb2 = base + 128;
            int c2 = nend - nb2; if (c2 > 128) c2 = 128;
            for (int l = tid; l < c2 * 4; l += 64) {
                int j = l >> 2, qd = (l & 3) * 4;
                cp16(&Kt[ns][j][qd], Kbase + (nb2 + j) * 128 + qd);
                cp16(&Vt[ns][j][qd], Vbase + (nb2 + j) * 128 + qd);
            }
            CP_COMMIT();
            asm volatile("cp.async.wait_group 1;" ::: "memory");
        } else {
            asm volatile("cp.async.wait_group 0;" ::: "memory");
        }
        __syncthreads();

        if (tid < 50) {
            for (int jw = 0; jw < cnt; jw += 32) {
                const unsigned mw0 = bits0[(base + jw) >> 5];
                const unsigned mw1 = bits1[(base + jw) >> 5];
                int wc = cnt - jw; if (wc > 32) wc = 32;
                #pragma unroll 4
                for (int jj = 0; jj < wc; ++jj) {
                    const int j = jw + jj;
                    const ulonglong2* kp = (const ulonglong2*)Kt[s][j];
                    ulonglong2 ka = kp[0], kb = kp[1], kc2 = kp[2], kd = kp[3];
                    u64t d0 = mul2(q0[0], ka.x);
                    u64t d1 = mul2(q0[1], ka.y);
                    d0 = fma2(q0[2], kb.x,  d0);
                    d1 = fma2(q0[3], kb.y,  d1);
                    d0 = fma2(q0[4], kc2.x, d0);
                    d1 = fma2(q0[5], kc2.y, d1);
                    d0 = fma2(q0[6], kd.x,  d0);
                    d1 = fma2(q0[7], kd.y,  d1);
                    u64t f0 = mul2(q1[0], ka.x);
                    u64t f1 = mul2(q1[1], ka.y);
                    f0 = fma2(q1[2], kb.x,  f0);
                    f1 = fma2(q1[3], kb.y,  f1);
                    f0 = fma2(q1[4], kc2.x, f0);
                    f1 = fma2(q1[5], kc2.y, f1);
                    f0 = fma2(q1[6], kd.x,  f0);
                    f1 = fma2(q1[7], kd.y,  f1);
                    float2 sv0 = unpack2(add2(d0, d1));
                    float2 sv1 = unpack2(add2(f0, f1));
                    float e0 = ex2f(sv0.x + sv0.y);
                    float e1 = ex2f(sv1.x + sv1.y);
                    if ((mw0 >> jj) & 1u) e0 = 0.f;
                    if ((mw1 >> jj) & 1u) e1 = 0.f;
                    ls0 += e0; ls1 += e1;
                    u64t E0 = splat2(e0), E1 = splat2(e1);
                    const ulonglong2* vp = (const ulonglong2*)Vt[s][j];
                    ulonglong2 va = vp[0], vb = vp[1], vc = vp[2], vd = vp[3];
                    a0[0] = fma2(E0, va.x, a0[0]); a0[1] = fma2(E0, va.y, a0[1]);
                    a0[2] = fma2(E0, vb.x, a0[2]); a0[3] = fma2(E0, vb.y, a0[3]);
                    a0[4] = fma2(E0, vc.x, a0[4]); a0[5] = fma2(E0, vc.y, a0[5]);
                    a0[6] = fma2(E0, vd.x, a0[6]); a0[7] = fma2(E0, vd.y, a0[7]);
                    a1[0] = fma2(E1, va.x, a1[0]); a1[1] = fma2(E1, va.y, a1[1]);
                    a1[2] = fma2(E1, vb.x, a1[2]); a1[3] = fma2(E1, vb.y, a1[3]);
                    a1[4] = fma2(E1, vc.x, a1[4]); a1[5] = fma2(E1, vc.y, a1[5]);
                    a1[6] = fma2(E1, vd.x, a1[6]); a1[7] = fma2(E1, vd.y, a1[7]);
                }
            }
        }
        __syncthreads();
    }

    if (tid < 50) {
        float* pp0 = g_part + ((split * 512 + bh) * 100 + tid) * 17;
        float* pp1 = g_part + ((split * 512 + bh) * 100 + tid + 50) * 17;
        #pragma unroll
        for (int i = 0; i < 8; ++i) {
            float2 u0 = unpack2(a0[i]);
            float2 u1 = unpack2(a1[i]);
            pp0[2 * i] = u0.x; pp0[2 * i + 1] = u0.y;
            pp1[2 * i] = u1.x; pp1[2 * i + 1] = u1.y;
        }
        pp0[16] = ls0;
        pp1[16] = ls1;
    }
}

// ============================================================================
// Kernel 3b: combine 4 attn splits -> g_O
// ============================================================================
__global__ void attn_combine() {
    const int u = blockIdx.x * 256 + threadIdx.x;
    if (u >= 512 * 100) return;
    const int bh = u / 100, p = u % 100;
    float acc[16]; float lsum = 0.f;
    #pragma unroll
    for (int i = 0; i < 16; ++i) acc[i] = 0.f;
    #pragma unroll
    for (int sp = 0; sp < 4; ++sp) {
        const float* pp = g_part + ((sp * 512 + bh) * 100 + p) * 17;
        #pragma unroll
        for (int i = 0; i < 16; ++i) acc[i] += pp[i];
        lsum += pp[16];
    }
    const float inv = 1.f / lsum;
    const int b = bh >> 3, h = bh & 7;
    float* op = g_O + (b * 100 + p) * 128 + h * 16;
    #pragma unroll
    for (int i = 0; i < 16; ++i) op[i] = acc[i] * inv;
}

// ============================================================================
// Kernel 4: MH = O @ Wc + bc. 16 rows/block, W streamed from L2, f32x2.
// ============================================================================
__global__ void __launch_bounds__(256)
mh_kernel(const float* __restrict__ Wc, const float* __restrict__ bc) {
    __shared__ float As[128][20];
    const int tid = threadIdx.x;
    const int R0  = blockIdx.x * 16;
    const int tx  = tid & 63;
    const int ty  = tid >> 6;

    for (int l = tid; l < 2048; l += 256) {
        int row = l >> 7, col = l & 127;
        As[col][row] = g_O[(R0 + row) * 128 + col];
    }
    __syncthreads();

    u64t acc[4];
    {
        float2 bb = *(const float2*)(bc + tx * 2);
        u64t bb2; asm("mov.b64 %0, {%1, %2};" : "=l"(bb2) : "f"(bb.x), "f"(bb.y));
        acc[0] = bb2; acc[1] = bb2; acc[2] = bb2; acc[3] = bb2;
    }

    #pragma unroll 8
    for (int k = 0; k < 128; ++k) {
        u64t w = *(const u64t*)(Wc + k * 128 + tx * 2);
        float4 a = *(const float4*)&As[k][ty * 4];
        acc[0] = fma2(splat2(a.x), w, acc[0]);
        acc[1] = fma2(splat2(a.y), w, acc[1]);
        acc[2] = fma2(splat2(a.z), w, acc[2]);
        acc[3] = fma2(splat2(a.w), w, acc[3]);
    }

    #pragma unroll
    for (int r = 0; r < 4; ++r)
        *(u64t*)(g_MH + (R0 + ty * 4 + r) * 128 + tx * 2) = acc[r];
}

// ============================================================================
// Kernel 5: score = MH @ E^T + fused heuristic/noise/tanh epilogue (no mask).
// ============================================================================
__global__ void __launch_bounds__(256, 2)
score_kernel(const float* __restrict__ Enodes,
             const float* __restrict__ cur_dist,
             const float* __restrict__ noise,
             float* __restrict__ out) {
    const int b   = blockIdx.z;
    const int p0  = blockIdx.y * 64;
    const int n0  = blockIdx.x * 128;
    const int tid = threadIdx.x;
    const int tx  = tid & 15, ty = tid >> 4;

    __shared__ float Es[32][132];
    __shared__ float Ms[32][68];

    u64t acc[16];
    #pragma unroll
    for (int i = 0; i < 16; ++i) acc[i] = 0ull;

    for (int kc = 0; kc < 128; kc += 32) {
        __syncthreads();
        for (int l = tid; l < 4096; l += 256) {
            int n = l >> 5, k = l & 31;
            Es[k][n] = (n0 + n < 1000) ? Enodes[(b * 1000 + n0 + n) * 128 + kc + k] : 0.f;
        }
        for (int l = tid; l < 2048; l += 256) {
            int pp = l >> 5, k = l & 31;
            int p = p0 + pp;
            Ms[k][pp] = (p < 100) ? g_MH[(b * 100 + p) * 128 + kc + k] : 0.f;
        }
        __syncthreads();

        #pragma unroll 4
        for (int k = 0; k < 32; ++k) {
            float4 mv = *(const float4*)&Ms[k][ty * 4];
            u64t m0 = splat2(mv.x), m1 = splat2(mv.y), m2 = splat2(mv.z), m3 = splat2(mv.w);
            const ulonglong2* ep = (const ulonglong2*)&Es[k][tx * 8];
            ulonglong2 e0 = ep[0], e1 = ep[1];
            acc[0]  = fma2(m0, e0.x, acc[0]);  acc[1]  = fma2(m0, e0.y, acc[1]);
            acc[2]  = fma2(m0, e1.x, acc[2]);  acc[3]  = fma2(m0, e1.y, acc[3]);
            acc[4]  = fma2(m1, e0.x, acc[4]);  acc[5]  = fma2(m1, e0.y, acc[5]);
            acc[6]  = fma2(m1, e1.x, acc[6]);  acc[7]  = fma2(m1, e1.y, acc[7]);
            acc[8]  = fma2(m2, e0.x, acc[8]);  acc[9]  = fma2(m2, e0.y, acc[9]);
            acc[10] = fma2(m2, e1.x, acc[10]); acc[11] = fma2(m2, e1.y, acc[11]);
            acc[12] = fma2(m3, e0.x, acc[12]); acc[13] = fma2(m3, e0.y, acc[13]);
            acc[14] = fma2(m3, e1.x, acc[14]); acc[15] = fma2(m3, e1.y, acc[15]);
        }
    }

    const int nbase = n0 + tx * 8;
    if (nbase >= 1000) return;
    #pragma unroll
    for (int r = 0; r < 4; ++r) {
        int p = p0 + ty * 4 + r;
        if (p < 100) {
            int idx = (b * 100 + p) * 1000 + nbase;
            float sv[8];
            #pragma unroll
            for (int c = 0; c < 4; ++c) {
                float2 u = unpack2(acc[r * 4 + c]);
                sv[2 * c] = u.x; sv[2 * c + 1] = u.y;
            }
            float4 cd0 = *(const float4*)(cur_dist + idx);
            float4 cd1 = *(const float4*)(cur_dist + idx + 4);
            float4 nz0 = *(const float4*)(noise + idx);
            float4 nz1 = *(const float4*)(noise + idx + 4);
            float cd[8] = {cd0.x, cd0.y, cd0.z, cd0.w, cd1.x, cd1.y, cd1.z, cd1.w};
            float nz[8] = {nz0.x, nz0.y, nz0.z, nz0.w, nz1.x, nz1.y, nz1.z, nz1.w};
            float res[8];
            #pragma unroll
            for (int j = 0; j < 8; ++j) {
                float heur = -__logf(fmaf(2.f, cd[j], 1e-6f));
                float s    = sv[j] * INV_SQRT_EMB + A_COEF * heur + B_COEF * nz[j];
                res[j]     = 10.f * tanhf(s);
            }
            *(float4*)(out + idx)     = make_float4(res[0], res[1], res[2], res[3]);
            *(float4*)(out + idx + 4) = make_float4(res[4], res[5], res[6], res[7]);
        }
    }
}

// ============================================================================
// Kernel 6: masked in-place row softmax. Scores bounded by 10*tanh => use
// constant shift M=10 (softmax is shift-invariant); no max pass needed.
// ============================================================================
__global__ void softmax_kernel(float* __restrict__ out) {
    const int row = blockIdx.x;
    const int tid = threadIdx.x;
    float* sp = out + row * 1000;

    __shared__ unsigned sbw[32];
    __shared__ float ssum[8];
    if (tid < 32) sbw[tid] = g_bits[row * 32 + tid];
    __syncthreads();

    float e[4], lsum = 0.f;
    #pragma unroll
    for (int t = 0; t < 4; ++t) {
        int n = tid + t * 256;
        float x = 0.f;
        if (n < 1000 && !((sbw[n >> 5] >> (n & 31)) & 1u))
            x = __expf(sp[n] - 10.f);
        e[t] = x; lsum += x;
    }
    #pragma unroll
    for (int o = 16; o; o >>= 1) lsum += __shfl_xor_sync(0xffffffffu, lsum, o);
    if ((tid & 31) == 0) ssum[tid >> 5] = lsum;
    __syncthreads();
    float S = 0.f;
    #pragma unroll
    for (int w = 0; w < 8; ++w) S += ssum[w];

    float inv = 1.f / S;
    #pragma unroll
    for (int t = 0; t < 4; ++t) {
        int n = tid + t * 256;
        if (n < 1000) sp[n] = e[t] * inv;
    }
}

// ============================================================================
extern "C" void kernel_launch(void* const* d_in, const int* in_sizes, int n_in,
                              void* d_out, int out_size) {
    const float* eln      = (const float*)d_in[0];
    const float* loadv    = (const float*)d_in[1];
    const float* timev    = (const float*)d_in[2];
    const float* cur_dist = (const float*)d_in[3];
    const float* ninf     = (const float*)d_in[4];
    const float* noise    = (const float*)d_in[5];
    const float* Enodes   = (const float*)d_in[6];
    const float* Wq       = (const float*)d_in[7];
    const float* Wk       = (const float*)d_in[8];
    const float* Wv       = (const float*)d_in[9];
    const float* Wc       = (const float*)d_in[10];
    const float* bc       = (const float*)d_in[11];
    float* out = (float*)d_out;

    bits_kernel<<<25600, 256>>>(ninf);
    kv_kernel<<<1000, 256>>>(Enodes, Wk, Wv);
    q_kernel<<<400, 128>>>(eln, loadv, timev, Wq);
    attn_kernel<<<dim3(512, 4), 64>>>();
    attn_combine<<<200, 256>>>();
    mh_kernel<<<400, 256>>>(Wc, bc);
    score_kernel<<<dim3(8, 2, 64), 256>>>(Enodes, cur_dist, noise, out);
    softmax_kernel<<<6400, 256>>>(out);
}

// round 5
// speedup vs baseline: 1.7302x; 1.0131x over previous
#include <cuda_runtime.h>
#include <math.h>

#define Bc   64
#define Pc   100
#define Nc   1000
#define EMBc 128

// ---- scratch (__device__ globals; no allocation allowed) ----
__device__ __align__(16) float g_K[Bc * Nc * EMBc];
__device__ __align__(16) float g_V[Bc * Nc * EMBc];
__device__ __align__(16) float g_Q[Bc * Pc * EMBc];
__device__ __align__(16) float g_O[Bc * Pc * EMBc];
__device__ __align__(16) float g_MH[Bc * Pc * EMBc];
__device__ __align__(16) unsigned g_bits[Bc * Pc * 32];          // packed mask
__device__ __align__(16) float g_part[4 * 512 * Pc * 17];        // attn split partials

constexpr double X218   = 3.814697265625e-06;
constexpr float  A_COEF = (float)(1.0 / (1.0 + X218));
constexpr float  B_COEF = (float)(1.0 - 1.0 / (1.0 + X218));
constexpr float  INV_SQRT_EMB = 0.08838834764831845f;
constexpr float  LOG2E = 1.44269504088896340736f;

// ---- packed fp32x2 helpers ----
typedef unsigned long long u64t;
__device__ __forceinline__ u64t fma2(u64t a, u64t b, u64t c) {
    u64t d; asm("fma.rn.f32x2 %0, %1, %2, %3;" : "=l"(d) : "l"(a), "l"(b), "l"(c)); return d;
}
__device__ __forceinline__ u64t mul2(u64t a, u64t b) {
    u64t d; asm("mul.rn.f32x2 %0, %1, %2;" : "=l"(d) : "l"(a), "l"(b)); return d;
}
__device__ __forceinline__ u64t add2(u64t a, u64t b) {
    u64t d; asm("add.rn.f32x2 %0, %1, %2;" : "=l"(d) : "l"(a), "l"(b)); return d;
}
__device__ __forceinline__ u64t splat2(float x) {
    u64t d; asm("mov.b64 %0, {%1, %1};" : "=l"(d) : "f"(x)); return d;
}
__device__ __forceinline__ float2 unpack2(u64t v) {
    float2 r; asm("mov.b64 {%0, %1}, %2;" : "=f"(r.x), "=f"(r.y) : "l"(v)); return r;
}
__device__ __forceinline__ float ex2f(float x) {
    float r; asm("ex2.approx.f32 %0, %1;" : "=f"(r) : "f"(x)); return r;
}
__device__ __forceinline__ float rcpf(float x) {
    float r; asm("rcp.approx.f32 %0, %1;" : "=f"(r) : "f"(x)); return r;
}
// tanh(x)*scale via exp form, NR-refined reciprocal. |err| ~1e-7.
__device__ __forceinline__ float tanh_scaled(float x, float scale) {
    float t = ex2f(x * (2.f * LOG2E));       // e^{2x}
    float num = t - 1.f, den = t + 1.f;
    float r = rcpf(den);
    r = r * (2.f - den * r);                 // one Newton step
    return num * r * scale;
}

// ---- cp.async helpers ----
__device__ __forceinline__ void cp16(void* dst, const void* src) {
    unsigned d = (unsigned)__cvta_generic_to_shared(dst);
    asm volatile("cp.async.cg.shared.global [%0], [%1], 16;" :: "r"(d), "l"(src));
}
#define CP_COMMIT() asm volatile("cp.async.commit_group;" ::: "memory")

// ============================================================================
// Kernel 0: pack ninf mask into bits (1 = masked).
// ============================================================================
__global__ void bits_kernel(const float* __restrict__ ninf) {
    const int w = blockIdx.x * 8 + (threadIdx.x >> 5);
    if (w >= Bc * Pc * 32) return;
    const int lane = threadIdx.x & 31;
    const int row = w >> 5, word = w & 31;
    const int n = word * 32 + lane;
    float v = -1.f;
    if (n < 1000) v = ninf[row * 1000 + n];
    unsigned m = __ballot_sync(0xffffffffu, v < -0.5f);
    if (lane == 0) g_bits[w] = m;
}

// ============================================================================
// Kernel 1: K = E @ Wk, V = E @ Wv. 64x128 tile, f32x2, cp.async double buffer.
// ============================================================================
__global__ void __launch_bounds__(256, 2)
kv_kernel(const float* __restrict__ E,
          const float* __restrict__ Wk,
          const float* __restrict__ Wv) {
    __shared__ __align__(16) float As[2][64][20];
    __shared__ __align__(16) float Wks[2][16][128];
    __shared__ __align__(16) float Wvs[2][16][128];
    const int tid = threadIdx.x;
    const int R0  = blockIdx.x * 64;
    const int tx  = tid & 15;
    const int ty  = tid >> 4;
    const int arow = tid >> 2, akq = (tid & 3) * 4;

    u64t accK[16], accV[16];
    #pragma unroll
    for (int i = 0; i < 16; ++i) { accK[i] = 0ull; accV[i] = 0ull; }

    {
        cp16(&As[0][arow][akq], E + (R0 + arow) * 128 + akq);
        #pragma unroll
        for (int i = 0; i < 2; ++i) {
            int l = tid + i * 256;
            int kr = l >> 5, c4 = (l & 31) * 4;
            cp16(&Wks[0][kr][c4], Wk + kr * 128 + c4);
            cp16(&Wvs[0][kr][c4], Wv + kr * 128 + c4);
        }
        CP_COMMIT();
    }

    for (int c = 0; c < 8; ++c) {
        const int s = c & 1;
        if (c + 1 < 8) {
            const int ns = 1 - s, kc = (c + 1) * 16;
            cp16(&As[ns][arow][akq], E + (R0 + arow) * 128 + kc + akq);
            #pragma unroll
            for (int i = 0; i < 2; ++i) {
                int l = tid + i * 256;
                int kr = l >> 5, c4 = (l & 31) * 4;
                cp16(&Wks[ns][kr][c4], Wk + (kc + kr) * 128 + c4);
                cp16(&Wvs[ns][kr][c4], Wv + (kc + kr) * 128 + c4);
            }
            CP_COMMIT();
            asm volatile("cp.async.wait_group 1;" ::: "memory");
        } else {
            asm volatile("cp.async.wait_group 0;" ::: "memory");
        }
        __syncthreads();

        #pragma unroll 4
        for (int k = 0; k < 16; ++k) {
            float a0f = As[s][ty * 4 + 0][k];
            float a1f = As[s][ty * 4 + 1][k];
            float a2f = As[s][ty * 4 + 2][k];
            float a3f = As[s][ty * 4 + 3][k];
            u64t a0 = splat2(a0f), a1 = splat2(a1f), a2 = splat2(a2f), a3 = splat2(a3f);
            const ulonglong2* wkp = (const ulonglong2*)&Wks[s][k][tx * 8];
            ulonglong2 wk0 = wkp[0], wk1 = wkp[1];
            const ulonglong2* wvp = (const ulonglong2*)&Wvs[s][k][tx * 8];
            ulonglong2 wv0 = wvp[0], wv1 = wvp[1];

            accK[0]  = fma2(a0, wk0.x, accK[0]);  accK[1]  = fma2(a0, wk0.y, accK[1]);
            accK[2]  = fma2(a0, wk1.x, accK[2]);  accK[3]  = fma2(a0, wk1.y, accK[3]);
            accK[4]  = fma2(a1, wk0.x, accK[4]);  accK[5]  = fma2(a1, wk0.y, accK[5]);
            accK[6]  = fma2(a1, wk1.x, accK[6]);  accK[7]  = fma2(a1, wk1.y, accK[7]);
            accK[8]  = fma2(a2, wk0.x, accK[8]);  accK[9]  = fma2(a2, wk0.y, accK[9]);
            accK[10] = fma2(a2, wk1.x, accK[10]); accK[11] = fma2(a2, wk1.y, accK[11]);
            accK[12] = fma2(a3, wk0.x, accK[12]); accK[13] = fma2(a3, wk0.y, accK[13]);
            accK[14] = fma2(a3, wk1.x, accK[14]); accK[15] = fma2(a3, wk1.y, accK[15]);

            accV[0]  = fma2(a0, wv0.x, accV[0]);  accV[1]  = fma2(a0, wv0.y, accV[1]);
            accV[2]  = fma2(a0, wv1.x, accV[2]);  accV[3]  = fma2(a0, wv1.y, accV[3]);
            accV[4]  = fma2(a1, wv0.x, accV[4]);  accV[5]  = fma2(a1, wv0.y, accV[5]);
            accV[6]  = fma2(a1, wv1.x, accV[6]);  accV[7]  = fma2(a1, wv1.y, accV[7]);
            accV[8]  = fma2(a2, wv0.x, accV[8]);  accV[9]  = fma2(a2, wv0.y, accV[9]);
            accV[10] = fma2(a2, wv1.x, accV[10]); accV[11] = fma2(a2, wv1.y, accV[11]);
            accV[12] = fma2(a3, wv0.x, accV[12]); accV[13] = fma2(a3, wv0.y, accV[13]);
            accV[14] = fma2(a3, wv1.x, accV[14]); accV[15] = fma2(a3, wv1.y, accV[15]);
        }
        __syncthreads();
    }

    #pragma unroll
    for (int r = 0; r < 4; ++r) {
        float* dk = g_K + (R0 + ty * 4 + r) * 128 + tx * 8;
        float* dv = g_V + (R0 + ty * 4 + r) * 128 + tx * 8;
        ulonglong2 t;
        t.x = accK[r * 4 + 0]; t.y = accK[r * 4 + 1]; ((ulonglong2*)dk)[0] = t;
        t.x = accK[r * 4 + 2]; t.y = accK[r * 4 + 3]; ((ulonglong2*)dk)[1] = t;
        t.x = accV[r * 4 + 0]; t.y = accV[r * 4 + 1]; ((ulonglong2*)dv)[0] = t;
        t.x = accV[r * 4 + 2]; t.y = accV[r * 4 + 3]; ((ulonglong2*)dv)[1] = t;
    }
}

// ============================================================================
// Kernel 2: Q = concat(eln, load, time) @ Wq
// ============================================================================
__global__ void q_kernel(const float* __restrict__ eln,
                         const float* __restrict__ loadv,
                         const float* __restrict__ timev,
                         const float* __restrict__ Wq) {
    __shared__ __align__(16) float sA[130][16];
    const int r0  = blockIdx.x * 16;
    const int tid = threadIdx.x;

    for (int l = tid; l < 130 * 16; l += 128) {
        int k = l >> 4, r = l & 15;
        int g = r0 + r;
        float v;
        if (k < 128)       v = eln[g * 128 + k];
        else if (k == 128) v = loadv[g];
        else               v = timev[g];
        sA[k][r] = v;
    }
    __syncthreads();

    const int c = tid;
    float acc[16];
    #pragma unroll
    for (int i = 0; i < 16; ++i) acc[i] = 0.f;

    for (int k = 0; k < 130; ++k) {
        float w = Wq[k * 128 + c];
        float a[16];
        const float4* ap = (const float4*)sA[k];
        ((float4*)a)[0] = ap[0]; ((float4*)a)[1] = ap[1];
        ((float4*)a)[2] = ap[2]; ((float4*)a)[3] = ap[3];
        #pragma unroll
        for (int i = 0; i < 16; ++i) acc[i] = fmaf(a[i], w, acc[i]);
    }
    #pragma unroll
    for (int i = 0; i < 16; ++i) g_Q[(r0 + i) * 128 + c] = acc[i];
}

// ============================================================================
// Kernel 3: attention. block = (bh, split of 256 n). 64 threads (2 warps);
// thread t<50 handles queries p=t and p=t+50. 64-row K/V tiles double-buffered
// (smem 16KB -> 8 blocks/SM, reg-limited).
// ============================================================================
__global__ void __launch_bounds__(64, 8)
attn_kernel() {
    const int bh    = blockIdx.x;
    const int split = blockIdx.y;
    const int b     = bh >> 3;
    const int h     = bh & 7;
    const int tid   = threadIdx.x;
    const int nbeg  = split * 256;
    const int nend  = (nbeg + 256 < 1000) ? (nbeg + 256) : 1000;

    __shared__ __align__(16) float Kt[2][64][16];
    __shared__ __align__(16) float Vt[2][64][16];

    const float* Kbase = g_K + b * 1000 * 128 + h * 16;
    const float* Vbase = g_V + b * 1000 * 128 + h * 16;

    // stage tile 0
    {
        int cnt0 = nend - nbeg; if (cnt0 > 64) cnt0 = 64;
        for (int l = tid; l < cnt0 * 4; l += 64) {
            int j = l >> 2, qd = (l & 3) * 4;
            cp16(&Kt[0][j][qd], Kbase + (nbeg + j) * 128 + qd);
            cp16(&Vt[0][j][qd], Vbase + (nbeg + j) * 128 + qd);
        }
        CP_COMMIT();
    }

    u64t q0[8], q1[8], a0[8], a1[8];
    #pragma unroll
    for (int i = 0; i < 8; ++i) { q0[i] = 0ull; q1[i] = 0ull; a0[i] = 0ull; a1[i] = 0ull; }
    float ls0 = 0.f, ls1 = 0.f;
    const unsigned* bits0 = g_bits;
    const unsigned* bits1 = g_bits;

    if (tid < 50) {
        const ulonglong2* qp0 = (const ulonglong2*)(g_Q + (b * 100 + tid) * 128 + h * 16);
        const ulonglong2* qp1 = (const ulonglong2*)(g_Q + (b * 100 + tid + 50) * 128 + h * 16);
        u64t qs = splat2(0.25f * LOG2E);
        #pragma unroll
        for (int i = 0; i < 4; ++i) {
            ulonglong2 t0 = qp0[i], t1 = qp1[i];
            q0[2 * i]     = mul2(t0.x, qs);
            q0[2 * i + 1] = mul2(t0.y, qs);
            q1[2 * i]     = mul2(t1.x, qs);
            q1[2 * i + 1] = mul2(t1.y, qs);
        }
        bits0 = g_bits + (b * 100 + tid) * 32;
        bits1 = g_bits + (b * 100 + tid + 50) * 32;
    }

    const int ntiles = (nend - nbeg + 63) >> 6;
    for (int t = 0; t < ntiles; ++t) {
        const int s    = t & 1;
        const int base = nbeg + t * 64;
        int cnt = nend - base; if (cnt > 64) cnt = 64;

        if (t + 1 < ntiles) {
            const int ns = 1 - s, nb2 = base + 64;
            int c2 = nend - nb2; if (c2 > 64) c2 = 64;
            for (int l = tid; l < c2 * 4; l += 64) {
                int j = l >> 2, qd = (l & 3) * 4;
                cp16(&Kt[ns][j][qd], Kbase + (nb2 + j) * 128 + qd);
                cp16(&Vt[ns][j][qd], Vbase + (nb2 + j) * 128 + qd);
            }
            CP_COMMIT();
            asm volatile("cp.async.wait_group 1;" ::: "memory");
        } else {
            asm volatile("cp.async.wait_group 0;" ::: "memory");
        }
        __syncthreads();

        if (tid < 50) {
            for (int jw = 0; jw < cnt; jw += 32) {
                const unsigned mw0 = bits0[(base + jw) >> 5];
                const unsigned mw1 = bits1[(base + jw) >> 5];
                int wc = cnt - jw; if (wc > 32) wc = 32;
                #pragma unroll 4
                for (int jj = 0; jj < wc; ++jj) {
                    const int j = jw + jj;
                    const ulonglong2* kp = (const ulonglong2*)Kt[s][j];
                    ulonglong2 ka = kp[0], kb = kp[1], kc2 = kp[2], kd = kp[3];
                    u64t d0 = mul2(q0[0], ka.x);
                    u64t d1 = mul2(q0[1], ka.y);
                    d0 = fma2(q0[2], kb.x,  d0);
                    d1 = fma2(q0[3], kb.y,  d1);
                    d0 = fma2(q0[4], kc2.x, d0);
                    d1 = fma2(q0[5], kc2.y, d1);
                    d0 = fma2(q0[6], kd.x,  d0);
                    d1 = fma2(q0[7], kd.y,  d1);
                    u64t f0 = mul2(q1[0], ka.x);
                    u64t f1 = mul2(q1[1], ka.y);
                    f0 = fma2(q1[2], kb.x,  f0);
                    f1 = fma2(q1[3], kb.y,  f1);
                    f0 = fma2(q1[4], kc2.x, f0);
                    f1 = fma2(q1[5], kc2.y, f1);
                    f0 = fma2(q1[6], kd.x,  f0);
                    f1 = fma2(q1[7], kd.y,  f1);
                    float2 sv0 = unpack2(add2(d0, d1));
                    float2 sv1 = unpack2(add2(f0, f1));
                    float e0 = ex2f(sv0.x + sv0.y);
                    float e1 = ex2f(sv1.x + sv1.y);
                    if ((mw0 >> jj) & 1u) e0 = 0.f;
                    if ((mw1 >> jj) & 1u) e1 = 0.f;
                    ls0 += e0; ls1 += e1;
                    u64t E0 = splat2(e0), E1 = splat2(e1);
                    const ulonglong2* vp = (const ulonglong2*)Vt[s][j];
                    ulonglong2 va = vp[0], vb = vp[1], vc = vp[2], vd = vp[3];
                    a0[0] = fma2(E0, va.x, a0[0]); a0[1] = fma2(E0, va.y, a0[1]);
                    a0[2] = fma2(E0, vb.x, a0[2]); a0[3] = fma2(E0, vb.y, a0[3]);
                    a0[4] = fma2(E0, vc.x, a0[4]); a0[5] = fma2(E0, vc.y, a0[5]);
                    a0[6] = fma2(E0, vd.x, a0[6]); a0[7] = fma2(E0, vd.y, a0[7]);
                    a1[0] = fma2(E1, va.x, a1[0]); a1[1] = fma2(E1, va.y, a1[1]);
                    a1[2] = fma2(E1, vb.x, a1[2]); a1[3] = fma2(E1, vb.y, a1[3]);
                    a1[4] = fma2(E1, vc.x, a1[4]); a1[5] = fma2(E1, vc.y, a1[5]);
                    a1[6] = fma2(E1, vd.x, a1[6]); a1[7] = fma2(E1, vd.y, a1[7]);
                }
            }
        }
        __syncthreads();
    }

    if (tid < 50) {
        float* pp0 = g_part + ((split * 512 + bh) * 100 + tid) * 17;
        float* pp1 = g_part + ((split * 512 + bh) * 100 + tid + 50) * 17;
        #pragma unroll
        for (int i = 0; i < 8; ++i) {
            float2 u0 = unpack2(a0[i]);
            float2 u1 = unpack2(a1[i]);
            pp0[2 * i] = u0.x; pp0[2 * i + 1] = u0.y;
            pp1[2 * i] = u1.x; pp1[2 * i + 1] = u1.y;
        }
        pp0[16] = ls0;
        pp1[16] = ls1;
    }
}

// ============================================================================
// Kernel 3b: combine 4 attn splits -> g_O
// ============================================================================
__global__ void attn_combine() {
    const int u = blockIdx.x * 256 + threadIdx.x;
    if (u >= 512 * 100) return;
    const int bh = u / 100, p = u % 100;
    float acc[16]; float lsum = 0.f;
    #pragma unroll
    for (int i = 0; i < 16; ++i) acc[i] = 0.f;
    #pragma unroll
    for (int sp = 0; sp < 4; ++sp) {
        const float* pp = g_part + ((sp * 512 + bh) * 100 + p) * 17;
        #pragma unroll
        for (int i = 0; i < 16; ++i) acc[i] += pp[i];
        lsum += pp[16];
    }
    const float inv = 1.f / lsum;
    const int b = bh >> 3, h = bh & 7;
    float* op = g_O + (b * 100 + p) * 128 + h * 16;
    #pragma unroll
    for (int i = 0; i < 16; ++i) op[i] = acc[i] * inv;
}

// ============================================================================
// Kernel 4: MH = O @ Wc + bc. 16 rows/block, W streamed from L2, f32x2.
// ============================================================================
__global__ void __launch_bounds__(256)
mh_kernel(const float* __restrict__ Wc, const float* __restrict__ bc) {
    __shared__ float As[128][20];
    const int tid = threadIdx.x;
    const int R0  = blockIdx.x * 16;
    const int tx  = tid & 63;
    const int ty  = tid >> 6;

    for (int l = tid; l < 2048; l += 256) {
        int row = l >> 7, col = l & 127;
        As[col][row] = g_O[(R0 + row) * 128 + col];
    }
    __syncthreads();

    u64t acc[4];
    {
        float2 bb = *(const float2*)(bc + tx * 2);
        u64t bb2; asm("mov.b64 %0, {%1, %2};" : "=l"(bb2) : "f"(bb.x), "f"(bb.y));
        acc[0] = bb2; acc[1] = bb2; acc[2] = bb2; acc[3] = bb2;
    }

    #pragma unroll 8
    for (int k = 0; k < 128; ++k) {
        u64t w = *(const u64t*)(Wc + k * 128 + tx * 2);
        float4 a = *(const float4*)&As[k][ty * 4];
        acc[0] = fma2(splat2(a.x), w, acc[0]);
        acc[1] = fma2(splat2(a.y), w, acc[1]);
        acc[2] = fma2(splat2(a.z), w, acc[2]);
        acc[3] = fma2(splat2(a.w), w, acc[3]);
    }

    #pragma unroll
    for (int r = 0; r < 4; ++r)
        *(u64t*)(g_MH + (R0 + ty * 4 + r) * 128 + tx * 2) = acc[r];
}

// ============================================================================
// Kernel 5: score = MH @ E^T + fused heuristic/noise/tanh epilogue (no mask).
// ============================================================================
__global__ void __launch_bounds__(256, 2)
score_kernel(const float* __restrict__ Enodes,
             const float* __restrict__ cur_dist,
             const float* __restrict__ noise,
             float* __restrict__ out) {
    const int b   = blockIdx.z;
    const int p0  = blockIdx.y * 64;
    const int n0  = blockIdx.x * 128;
    const int tid = threadIdx.x;
    const int tx  = tid & 15, ty = tid >> 4;

    __shared__ float Es[32][132];
    __shared__ float Ms[32][68];

    u64t acc[16];
    #pragma unroll
    for (int i = 0; i < 16; ++i) acc[i] = 0ull;

    for (int kc = 0; kc < 128; kc += 32) {
        __syncthreads();
        for (int l = tid; l < 4096; l += 256) {
            int n = l >> 5, k = l & 31;
            Es[k][n] = (n0 + n < 1000) ? Enodes[(b * 1000 + n0 + n) * 128 + kc + k] : 0.f;
        }
        for (int l = tid; l < 2048; l += 256) {
            int pp = l >> 5, k = l & 31;
            int p = p0 + pp;
            Ms[k][pp] = (p < 100) ? g_MH[(b * 100 + p) * 128 + kc + k] : 0.f;
        }
        __syncthreads();

        #pragma unroll 4
        for (int k = 0; k < 32; ++k) {
            float4 mv = *(const float4*)&Ms[k][ty * 4];
            u64t m0 = splat2(mv.x), m1 = splat2(mv.y), m2 = splat2(mv.z), m3 = splat2(mv.w);
            const ulonglong2* ep = (const ulonglong2*)&Es[k][tx * 8];
            ulonglong2 e0 = ep[0], e1 = ep[1];
            acc[0]  = fma2(m0, e0.x, acc[0]);  acc[1]  = fma2(m0, e0.y, acc[1]);
            acc[2]  = fma2(m0, e1.x, acc[2]);  acc[3]  = fma2(m0, e1.y, acc[3]);
            acc[4]  = fma2(m1, e0.x, acc[4]);  acc[5]  = fma2(m1, e0.y, acc[5]);
            acc[6]  = fma2(m1, e1.x, acc[6]);  acc[7]  = fma2(m1, e1.y, acc[7]);
            acc[8]  = fma2(m2, e0.x, acc[8]);  acc[9]  = fma2(m2, e0.y, acc[9]);
            acc[10] = fma2(m2, e1.x, acc[10]); acc[11] = fma2(m2, e1.y, acc[11]);
            acc[12] = fma2(m3, e0.x, acc[12]); acc[13] = fma2(m3, e0.y, acc[13]);
            acc[14] = fma2(m3, e1.x, acc[14]); acc[15] = fma2(m3, e1.y, acc[15]);
        }
    }

    const int nbase = n0 + tx * 8;
    if (nbase >= 1000) return;
    #pragma unroll
    for (int r = 0; r < 4; ++r) {
        int p = p0 + ty * 4 + r;
        if (p < 100) {
            int idx = (b * 100 + p) * 1000 + nbase;
            float sv[8];
            #pragma unroll
            for (int c = 0; c < 4; ++c) {
                float2 u = unpack2(acc[r * 4 + c]);
                sv[2 * c] = u.x; sv[2 * c + 1] = u.y;
            }
            float4 cd0 = *(const float4*)(cur_dist + idx);
            float4 cd1 = *(const float4*)(cur_dist + idx + 4);
            float4 nz0 = *(const float4*)(noise + idx);
            float4 nz1 = *(const float4*)(noise + idx + 4);
            float cd[8] = {cd0.x, cd0.y, cd0.z, cd0.w, cd1.x, cd1.y, cd1.z, cd1.w};
            float nz[8] = {nz0.x, nz0.y, nz0.z, nz0.w, nz1.x, nz1.y, nz1.z, nz1.w};
            float res[8];
            #pragma unroll
            for (int j = 0; j < 8; ++j) {
                float heur = -__logf(fmaf(2.f, cd[j], 1e-6f));
                float s    = sv[j] * INV_SQRT_EMB + A_COEF * heur + B_COEF * nz[j];
                res[j]     = tanh_scaled(s, 10.f);
            }
            *(float4*)(out + idx)     = make_float4(res[0], res[1], res[2], res[3]);
            *(float4*)(out + idx + 4) = make_float4(res[4], res[5], res[6], res[7]);
        }
    }
}

// ============================================================================
// Kernel 6: masked in-place row softmax, constant shift M=10.
// ============================================================================
__global__ void softmax_kernel(float* __restrict__ out) {
    const int row = blockIdx.x;
    const int tid = threadIdx.x;
    float* sp = out + row * 1000;

    __shared__ unsigned sbw[32];
    __shared__ float ssum[8];
    if (tid < 32) sbw[tid] = g_bits[row * 32 + tid];
    __syncthreads();

    float e[4], lsum = 0.f;
    #pragma unroll
    for (int t = 0; t < 4; ++t) {
        int n = tid + t * 256;
        float x = 0.f;
        if (n < 1000 && !((sbw[n >> 5] >> (n & 31)) & 1u))
            x = __expf(sp[n] - 10.f);
        e[t] = x; lsum += x;
    }
    #pragma unroll
    for (int o = 16; o; o >>= 1) lsum += __shfl_xor_sync(0xffffffffu, lsum, o);
    if ((tid & 31) == 0) ssum[tid >> 5] = lsum;
    __syncthreads();
    float S = 0.f;
    #pragma unroll
    for (int w = 0; w < 8; ++w) S += ssum[w];

    float inv = 1.f / S;
    #pragma unroll
    for (int t = 0; t < 4; ++t) {
        int n = tid + t * 256;
        if (n < 1000) sp[n] = e[t] * inv;
    }
}

// ============================================================================
extern "C" void kernel_launch(void* const* d_in, const int* in_sizes, int n_in,
                              void* d_out, int out_size) {
    const float* eln      = (const float*)d_in[0];
    const float* loadv    = (const float*)d_in[1];
    const float* timev    = (const float*)d_in[2];
    const float* cur_dist = (const float*)d_in[3];
    const float* ninf     = (const float*)d_in[4];
    const float* noise    = (const float*)d_in[5];
    const float* Enodes   = (const float*)d_in[6];
    const float* Wq       = (const float*)d_in[7];
    const float* Wk       = (const float*)d_in[8];
    const float* Wv       = (const float*)d_in[9];
    const float* Wc       = (const float*)d_in[10];
    const float* bc       = (const float*)d_in[11];
    float* out = (float*)d_out;

    bits_kernel<<<25600, 256>>>(ninf);
    kv_kernel<<<1000, 256>>>(Enodes, Wk, Wv);
    q_kernel<<<400, 128>>>(eln, loadv, timev, Wq);
    attn_kernel<<<dim3(512, 4), 64>>>();
    attn_combine<<<200, 256>>>();
    mh_kernel<<<400, 256>>>(Wc, bc);
    score_kernel<<<dim3(8, 2, 64), 256>>>(Enodes, cur_dist, noise, out);
    softmax_kernel<<<6400, 256>>>(out);
}

// round 7
// speedup vs baseline: 2.1953x; 1.2688x over previous
#include <cuda_runtime.h>
#include <cuda_bf16.h>
#include <math.h>
#include <stdint.h>

#define Bc   64
#define Pc   100
#define Nc   1000
#define EMBc 128

// ---- scratch (__device__ globals; no allocation allowed) ----
__device__ __align__(16) float g_K[Bc * Nc * EMBc];
__device__ __align__(16) float g_V[Bc * Nc * EMBc];
__device__ __align__(16) float g_Q[Bc * Pc * EMBc];
__device__ __align__(16) float g_O[Bc * Pc * EMBc];
__device__ __align__(16) float g_MH[Bc * Pc * EMBc];
__device__ __align__(16) unsigned g_bits[Bc * Pc * 32];
__device__ __align__(16) float g_part[4 * 512 * Pc * 17];
// W in mma.sync B-fragment order: [mat][n(128)][kk(8)][q(4)] x uint4{b0h,b1h,b0l,b1l}
__device__ __align__(16) uint4 g_Wfrag[2 * 128 * 8 * 4];

constexpr double X218   = 3.814697265625e-06;
constexpr float  A_COEF = (float)(1.0 / (1.0 + X218));
constexpr float  B_COEF = (float)(1.0 - 1.0 / (1.0 + X218));
constexpr float  INV_SQRT_EMB = 0.08838834764831845f;
constexpr float  LOG2E = 1.44269504088896340736f;

// ---- packed fp32x2 helpers ----
typedef unsigned long long u64t;
__device__ __forceinline__ u64t fma2(u64t a, u64t b, u64t c) {
    u64t d; asm("fma.rn.f32x2 %0, %1, %2, %3;" : "=l"(d) : "l"(a), "l"(b), "l"(c)); return d;
}
__device__ __forceinline__ u64t mul2(u64t a, u64t b) {
    u64t d; asm("mul.rn.f32x2 %0, %1, %2;" : "=l"(d) : "l"(a), "l"(b)); return d;
}
__device__ __forceinline__ u64t add2(u64t a, u64t b) {
    u64t d; asm("add.rn.f32x2 %0, %1, %2;" : "=l"(d) : "l"(a), "l"(b)); return d;
}
__device__ __forceinline__ u64t splat2(float x) {
    u64t d; asm("mov.b64 %0, {%1, %1};" : "=l"(d) : "f"(x)); return d;
}
__device__ __forceinline__ float2 unpack2(u64t v) {
    float2 r; asm("mov.b64 {%0, %1}, %2;" : "=f"(r.x), "=f"(r.y) : "l"(v)); return r;
}
__device__ __forceinline__ float ex2f(float x) {
    float r; asm("ex2.approx.f32 %0, %1;" : "=f"(r) : "f"(x)); return r;
}
__device__ __forceinline__ float rcpf(float x) {
    float r; asm("rcp.approx.f32 %0, %1;" : "=f"(r) : "f"(x)); return r;
}
__device__ __forceinline__ float tanh_scaled(float x, float scale) {
    float t = ex2f(x * (2.f * LOG2E));
    float num = t - 1.f, den = t + 1.f;
    float r = rcpf(den);
    r = r * (2.f - den * r);
    return num * r * scale;
}

// ---- cp.async ----
__device__ __forceinline__ void cp16(void* dst, const void* src) {
    unsigned d = (unsigned)__cvta_generic_to_shared(dst);
    asm volatile("cp.async.cg.shared.global [%0], [%1], 16;" :: "r"(d), "l"(src));
}
#define CP_COMMIT() asm volatile("cp.async.commit_group;" ::: "memory")

// ---- bf16 split helpers ----
__device__ __forceinline__ unsigned packbf2(float a, float b) {
    __nv_bfloat162 v = __floats2bfloat162_rn(a, b);
    return *reinterpret_cast<unsigned*>(&v);
}
__device__ __forceinline__ float bfrt(float x) {
    return __bfloat162float(__float2bfloat16(x));
}

// ---- mma.sync m16n8k16 bf16, fp32 accum (baseline PTX; HMMA on sm_103) ----
__device__ __forceinline__ void mma16816(float& d0, float& d1, float& d2, float& d3,
                                         unsigned a0, unsigned a1, unsigned a2, unsigned a3,
                                         unsigned b0, unsigned b1) {
    asm volatile(
        "mma.sync.aligned.m16n8k16.row.col.f32.bf16.bf16.f32 "
        "{%0,%1,%2,%3}, {%4,%5,%6,%7}, {%8,%9}, {%0,%1,%2,%3};"
        : "+f"(d0), "+f"(d1), "+f"(d2), "+f"(d3)
        : "r"(a0), "r"(a1), "r"(a2), "r"(a3), "r"(b0), "r"(b1));
}

// ============================================================================
// Kernel 0: pack ninf mask into bits (1 = masked).
// ============================================================================
__global__ void bits_kernel(const float* __restrict__ ninf) {
    const int w = blockIdx.x * 8 + (threadIdx.x >> 5);
    if (w >= Bc * Pc * 32) return;
    const int lane = threadIdx.x & 31;
    const int row = w >> 5, word = w & 31;
    const int n = word * 32 + lane;
    float v = -1.f;
    if (n < 1000) v = ninf[row * 1000 + n];
    unsigned m = __ballot_sync(0xffffffffu, v < -0.5f);
    if (lane == 0) g_bits[w] = m;
}

// ============================================================================
// Kernel 0b: pack W into B-fragment order (hi/lo bf16 split).
// Fragment (m16n8k16 col-major B): lane(n' = lane>>2, q = lane&3) holds
// b0={W[k][n],W[k+1][n]}, b1={W[k+8][n],W[k+9][n]}, k = kk*16 + q*2.
// ============================================================================
__global__ void wprep_kernel(const float* __restrict__ Wk, const float* __restrict__ Wv) {
    int idx = blockIdx.x * 256 + threadIdx.x;   // 8192 uint4 entries
    if (idx >= 8192) return;
    const int mat = idx >> 12;
    const int n   = (idx >> 5) & 127;
    const int kk  = (idx >> 2) & 7;
    const int q   = idx & 3;
    const int k   = kk * 16 + q * 2;
    const float* W = mat ? Wv : Wk;
    float w0 = W[k * 128 + n],       w1 = W[(k + 1) * 128 + n];
    float w2 = W[(k + 8) * 128 + n], w3 = W[(k + 9) * 128 + n];
    uint4 v;
    v.x = packbf2(w0, w1);
    v.y = packbf2(w2, w3);
    v.z = packbf2(w0 - bfrt(w0), w1 - bfrt(w1));
    v.w = packbf2(w2 - bfrt(w2), w3 - bfrt(w3));
    g_Wfrag[idx] = v;
}

// ============================================================================
// Kernel 1: K/V = E @ W via mma.sync bf16 hi/lo split (3-term, fp32 accum).
// grid (500, 2): x = 128-row E tile, y = matrix (0=K, 1=V). 8 warps = 4x2;
// warp tile 32 rows x 64 cols. A staged fp32 in smem; B frags LDG.128 from L2.
// ============================================================================
__global__ void __launch_bounds__(256, 2)
kv_mma_kernel(const float* __restrict__ E) {
    extern __shared__ __align__(16) float Es[];   // [128][132]
    const int tid  = threadIdx.x;
    const int wid  = tid >> 5;
    const int lane = tid & 31;
    const int R0   = blockIdx.x * 128;
    const int mat  = blockIdx.y;
    const int wr   = wid >> 1;          // warp row group (rows wr*32..+31)
    const int wc   = wid & 1;           // warp col group (cols wc*64..+63)

    // stage A tile (128 x 128 fp32, row stride 132)
    for (int l = tid; l < 4096; l += 256) {
        int row = l >> 5, q = l & 31;
        cp16(&Es[row * 132 + q * 4], E + (R0 + row) * 128 + q * 4);
    }
    CP_COMMIT();

    float acc[2][8][4];
    #pragma unroll
    for (int mt = 0; mt < 2; ++mt)
        #pragma unroll
        for (int nt = 0; nt < 8; ++nt)
            #pragma unroll
            for (int i = 0; i < 4; ++i) acc[mt][nt][i] = 0.f;

    const int rfrag = lane >> 2;            // 0..7
    const int cfrag = (lane & 3) * 2;       // 0,2,4,6
    const uint4* Wf = g_Wfrag + mat * 4096;

    asm volatile("cp.async.wait_group 0;" ::: "memory");
    __syncthreads();

    #pragma unroll
    for (int kk = 0; kk < 8; ++kk) {
        unsigned ahi[2][4], alo[2][4];
        #pragma unroll
        for (int mt = 0; mt < 2; ++mt) {
            const float* r0p = &Es[(wr * 32 + mt * 16 + rfrag) * 132 + kk * 16 + cfrag];
            const float* r8p = r0p + 8 * 132;
            float2 x0 = *(const float2*)r0p;
            float2 x1 = *(const float2*)r8p;
            float2 x2 = *(const float2*)(r0p + 8);
            float2 x3 = *(const float2*)(r8p + 8);
            ahi[mt][0] = packbf2(x0.x, x0.y);
            ahi[mt][1] = packbf2(x1.x, x1.y);
            ahi[mt][2] = packbf2(x2.x, x2.y);
            ahi[mt][3] = packbf2(x3.x, x3.y);
            alo[mt][0] = packbf2(x0.x - bfrt(x0.x), x0.y - bfrt(x0.y));
            alo[mt][1] = packbf2(x1.x - bfrt(x1.x), x1.y - bfrt(x1.y));
            alo[mt][2] = packbf2(x2.x - bfrt(x2.x), x2.y - bfrt(x2.y));
            alo[mt][3] = packbf2(x3.x - bfrt(x3.x), x3.y - bfrt(x3.y));
        }
        #pragma unroll
        for (int nt = 0; nt < 8; ++nt) {
            const int n = wc * 64 + nt * 8 + rfrag;
            uint4 bf = Wf[(n * 8 + kk) * 4 + (lane & 3)];
            #pragma unroll
            for (int mt = 0; mt < 2; ++mt) {
                mma16816(acc[mt][nt][0], acc[mt][nt][1], acc[mt][nt][2], acc[mt][nt][3],
                         ahi[mt][0], ahi[mt][1], ahi[mt][2], ahi[mt][3], bf.x, bf.y);
                mma16816(acc[mt][nt][0], acc[mt][nt][1], acc[mt][nt][2], acc[mt][nt][3],
                         alo[mt][0], alo[mt][1], alo[mt][2], alo[mt][3], bf.x, bf.y);
                mma16816(acc[mt][nt][0], acc[mt][nt][1], acc[mt][nt][2], acc[mt][nt][3],
                         ahi[mt][0], ahi[mt][1], ahi[mt][2], ahi[mt][3], bf.z, bf.w);
            }
        }
    }

    float* dst = (mat ? g_V : g_K);
    #pragma unroll
    for (int mt = 0; mt < 2; ++mt) {
        const int row = R0 + wr * 32 + mt * 16 + rfrag;
        #pragma unroll
        for (int nt = 0; nt < 8; ++nt) {
            const int col = wc * 64 + nt * 8 + cfrag;
            *(float2*)(dst + (size_t)row * 128 + col)       = make_float2(acc[mt][nt][0], acc[mt][nt][1]);
            *(float2*)(dst + (size_t)(row + 8) * 128 + col) = make_float2(acc[mt][nt][2], acc[mt][nt][3]);
        }
    }
}

// ============================================================================
// Kernel 2: Q = concat(eln, load, time) @ Wq
// ============================================================================
__global__ void q_kernel(const float* __restrict__ eln,
                         const float* __restrict__ loadv,
                         const float* __restrict__ timev,
                         const float* __restrict__ Wq) {
    __shared__ __align__(16) float sA[130][16];
    const int r0  = blockIdx.x * 16;
    const int tid = threadIdx.x;

    for (int l = tid; l < 130 * 16; l += 128) {
        int k = l >> 4, r = l & 15;
        int g = r0 + r;
        float v;
        if (k < 128)       v = eln[g * 128 + k];
        else if (k == 128) v = loadv[g];
        else               v = timev[g];
        sA[k][r] = v;
    }
    __syncthreads();

    const int c = tid;
    float acc[16];
    #pragma unroll
    for (int i = 0; i < 16; ++i) acc[i] = 0.f;

    for (int k = 0; k < 130; ++k) {
        float w = Wq[k * 128 + c];
        float a[16];
        const float4* ap = (const float4*)sA[k];
        ((float4*)a)[0] = ap[0]; ((float4*)a)[1] = ap[1];
        ((float4*)a)[2] = ap[2]; ((float4*)a)[3] = ap[3];
        #pragma unroll
        for (int i = 0; i < 16; ++i) acc[i] = fmaf(a[i], w, acc[i]);
    }
    #pragma unroll
    for (int i = 0; i < 16; ++i) g_Q[(r0 + i) * 128 + c] = acc[i];
}

// ============================================================================
// Kernel 3: attention (round-5 version, unchanged)
// ============================================================================
__global__ void __launch_bounds__(64, 8)
attn_kernel() {
    const int bh    = blockIdx.x;
    const int split = blockIdx.y;
    const int b     = bh >> 3;
    const int h     = bh & 7;
    const int tid   = threadIdx.x;
    const int nbeg  = split * 256;
    const int nend  = (nbeg + 256 < 1000) ? (nbeg + 256) : 1000;

    __shared__ __align__(16) float Kt[2][64][16];
    __shared__ __align__(16) float Vt[2][64][16];

    const float* Kbase = g_K + b * 1000 * 128 + h * 16;
    const float* Vbase = g_V + b * 1000 * 128 + h * 16;

    {
        int cnt0 = nend - nbeg; if (cnt0 > 64) cnt0 = 64;
        for (int l = tid; l < cnt0 * 4; l += 64) {
            int j = l >> 2, qd = (l & 3) * 4;
            cp16(&Kt[0][j][qd], Kbase + (nbeg + j) * 128 + qd);
            cp16(&Vt[0][j][qd], Vbase + (nbeg + j) * 128 + qd);
        }
        CP_COMMIT();
    }

    u64t q0[8], q1[8], a0[8], a1[8];
    #pragma unroll
    for (int i = 0; i < 8; ++i) { q0[i] = 0ull; q1[i] = 0ull; a0[i] = 0ull; a1[i] = 0ull; }
    float ls0 = 0.f, ls1 = 0.f;
    const unsigned* bits0 = g_bits;
    const unsigned* bits1 = g_bits;

    if (tid < 50) {
        const ulonglong2* qp0 = (const ulonglong2*)(g_Q + (b * 100 + tid) * 128 + h * 16);
        const ulonglong2* qp1 = (const ulonglong2*)(g_Q + (b * 100 + tid + 50) * 128 + h * 16);
        u64t qs = splat2(0.25f * LOG2E);
        #pragma unroll
        for (int i = 0; i < 4; ++i) {
            ulonglong2 t0 = qp0[i], t1 = qp1[i];
            q0[2 * i]     = mul2(t0.x, qs);
            q0[2 * i + 1] = mul2(t0.y, qs);
            q1[2 * i]     = mul2(t1.x, qs);
            q1[2 * i + 1] = mul2(t1.y, qs);
        }
        bits0 = g_bits + (b * 100 + tid) * 32;
        bits1 = g_bits + (b * 100 + tid + 50) * 32;
    }

    const int ntiles = (nend - nbeg + 63) >> 6;
    for (int t = 0; t < ntiles; ++t) {
        const int s    = t & 1;
        const int base = nbeg + t * 64;
        int cnt = nend - base; if (cnt > 64) cnt = 64;

        if (t + 1 < ntiles) {
            const int ns = 1 - s, nb2 = base + 64;
            int c2 = nend - nb2; if (c2 > 64) c2 = 64;
            for (int l = tid; l < c2 * 4; l += 64) {
                int j = l >> 2, qd = (l & 3) * 4;
                cp16(&Kt[ns][j][qd], Kbase + (nb2 + j) * 128 + qd);
                cp16(&Vt[ns][j][qd], Vbase + (nb2 + j) * 128 + qd);
            }
            CP_COMMIT();
            asm volatile("cp.async.wait_group 1;" ::: "memory");
        } else {
            asm volatile("cp.async.wait_group 0;" ::: "memory");
        }
        __syncthreads();

        if (tid < 50) {
            for (int jw = 0; jw < cnt; jw += 32) {
                const unsigned mw0 = bits0[(base + jw) >> 5];
                const unsigned mw1 = bits1[(base + jw) >> 5];
                int wc2 = cnt - jw; if (wc2 > 32) wc2 = 32;
                #pragma unroll 4
                for (int jj = 0; jj < wc2; ++jj) {
                    const int j = jw + jj;
                    const ulonglong2* kp = (const ulonglong2*)Kt[s][j];
                    ulonglong2 ka = kp[0], kb = kp[1], kc2 = kp[2], kd = kp[3];
                    u64t d0 = mul2(q0[0], ka.x);
                    u64t d1 = mul2(q0[1], ka.y);
                    d0 = fma2(q0[2], kb.x,  d0);
                    d1 = fma2(q0[3], kb.y,  d1);
                    d0 = fma2(q0[4], kc2.x, d0);
                    d1 = fma2(q0[5], kc2.y, d1);
                    d0 = fma2(q0[6], kd.x,  d0);
                    d1 = fma2(q0[7], kd.y,  d1);
                    u64t f0 = mul2(q1[0], ka.x);
                    u64t f1 = mul2(q1[1], ka.y);
                    f0 = fma2(q1[2], kb.x,  f0);
                    f1 = fma2(q1[3], kb.y,  f1);
                    f0 = fma2(q1[4], kc2.x, f0);
                    f1 = fma2(q1[5], kc2.y, f1);
                    f0 = fma2(q1[6], kd.x,  f0);
                    f1 = fma2(q1[7], kd.y,  f1);
                    float2 sv0 = unpack2(add2(d0, d1));
                    float2 sv1 = unpack2(add2(f0, f1));
                    float e0 = ex2f(sv0.x + sv0.y);
                    float e1 = ex2f(sv1.x + sv1.y);
                    if ((mw0 >> jj) & 1u) e0 = 0.f;
                    if ((mw1 >> jj) & 1u) e1 = 0.f;
                    ls0 += e0; ls1 += e1;
                    u64t E0 = splat2(e0), E1 = splat2(e1);
                    const ulonglong2* vp = (const ulonglong2*)Vt[s][j];
                    ulonglong2 va = vp[0], vb = vp[1], vc = vp[2], vd = vp[3];
                    a0[0] = fma2(E0, va.x, a0[0]); a0[1] = fma2(E0, va.y, a0[1]);
                    a0[2] = fma2(E0, vb.x, a0[2]); a0[3] = fma2(E0, vb.y, a0[3]);
                    a0[4] = fma2(E0, vc.x, a0[4]); a0[5] = fma2(E0, vc.y, a0[5]);
                    a0[6] = fma2(E0, vd.x, a0[6]); a0[7] = fma2(E0, vd.y, a0[7]);
                    a1[0] = fma2(E1, va.x, a1[0]); a1[1] = fma2(E1, va.y, a1[1]);
                    a1[2] = fma2(E1, vb.x, a1[2]); a1[3] = fma2(E1, vb.y, a1[3]);
                    a1[4] = fma2(E1, vc.x, a1[4]); a1[5] = fma2(E1, vc.y, a1[5]);
                    a1[6] = fma2(E1, vd.x, a1[6]); a1[7] = fma2(E1, vd.y, a1[7]);
                }
            }
        }
        __syncthreads();
    }

    if (tid < 50) {
        float* pp0 = g_part + ((split * 512 + bh) * 100 + tid) * 17;
        float* pp1 = g_part + ((split * 512 + bh) * 100 + tid + 50) * 17;
        #pragma unroll
        for (int i = 0; i < 8; ++i) {
            float2 u0 = unpack2(a0[i]);
            float2 u1 = unpack2(a1[i]);
            pp0[2 * i] = u0.x; pp0[2 * i + 1] = u0.y;
            pp1[2 * i] = u1.x; pp1[2 * i + 1] = u1.y;
        }
        pp0[16] = ls0;
        pp1[16] = ls1;
    }
}

// ============================================================================
// Kernel 3b: combine 4 attn splits -> g_O
// ============================================================================
__global__ void attn_combine() {
    const int u = blockIdx.x * 256 + threadIdx.x;
    if (u >= 512 * 100) return;
    const int bh = u / 100, p = u % 100;
    float acc[16]; float lsum = 0.f;
    #pragma unroll
    for (int i = 0; i < 16; ++i) acc[i] = 0.f;
    #pragma unroll
    for (int sp = 0; sp < 4; ++sp) {
        const float* pp = g_part + ((sp * 512 + bh) * 100 + p) * 17;
        #pragma unroll
        for (int i = 0; i < 16; ++i) acc[i] += pp[i];
        lsum += pp[16];
    }
    const float inv = 1.f / lsum;
    const int b = bh >> 3, h = bh & 7;
    float* op = g_O + (b * 100 + p) * 128 + h * 16;
    #pragma unroll
    for (int i = 0; i < 16; ++i) op[i] = acc[i] * inv;
}

// ============================================================================
// Kernel 4: MH = O @ Wc + bc
// ============================================================================
__global__ void __launch_bounds__(256)
mh_kernel(const float* __restrict__ Wc, const float* __restrict__ bc) {
    __shared__ float As[128][20];
    const int tid = threadIdx.x;
    const int R0  = blockIdx.x * 16;
    const int tx  = tid & 63;
    const int ty  = tid >> 6;

    for (int l = tid; l < 2048; l += 256) {
        int row = l >> 7, col = l & 127;
        As[col][row] = g_O[(R0 + row) * 128 + col];
    }
    __syncthreads();

    u64t acc[4];
    {
        float2 bb = *(const float2*)(bc + tx * 2);
        u64t bb2; asm("mov.b64 %0, {%1, %2};" : "=l"(bb2) : "f"(bb.x), "f"(bb.y));
        acc[0] = bb2; acc[1] = bb2; acc[2] = bb2; acc[3] = bb2;
    }

    #pragma unroll 8
    for (int k = 0; k < 128; ++k) {
        u64t w = *(const u64t*)(Wc + k * 128 + tx * 2);
        float4 a = *(const float4*)&As[k][ty * 4];
        acc[0] = fma2(splat2(a.x), w, acc[0]);
        acc[1] = fma2(splat2(a.y), w, acc[1]);
        acc[2] = fma2(splat2(a.z), w, acc[2]);
        acc[3] = fma2(splat2(a.w), w, acc[3]);
    }

    #pragma unroll
    for (int r = 0; r < 4; ++r)
        *(u64t*)(g_MH + (R0 + ty * 4 + r) * 128 + tx * 2) = acc[r];
}

// ============================================================================
// Kernel 5: score = MH @ E^T + fused epilogue
// ============================================================================
__global__ void __launch_bounds__(256, 2)
score_kernel(const float* __restrict__ Enodes,
             const float* __restrict__ cur_dist,
             const float* __restrict__ noise,
             float* __restrict__ out) {
    const int b   = blockIdx.z;
    const int p0  = blockIdx.y * 64;
    const int n0  = blockIdx.x * 128;
    const int tid = threadIdx.x;
    const int tx  = tid & 15, ty = tid >> 4;

    __shared__ float Es[32][132];
    __shared__ float Ms[32][68];

    u64t acc[16];
    #pragma unroll
    for (int i = 0; i < 16; ++i) acc[i] = 0ull;

    for (int kc = 0; kc < 128; kc += 32) {
        __syncthreads();
        for (int l = tid; l < 4096; l += 256) {
            int n = l >> 5, k = l & 31;
            Es[k][n] = (n0 + n < 1000) ? Enodes[(b * 1000 + n0 + n) * 128 + kc + k] : 0.f;
        }
        for (int l = tid; l < 2048; l += 256) {
            int pp = l >> 5, k = l & 31;
            int p = p0 + pp;
            Ms[k][pp] = (p < 100) ? g_MH[(b * 100 + p) * 128 + kc + k] : 0.f;
        }
        __syncthreads();

        #pragma unroll 4
        for (int k = 0; k < 32; ++k) {
            float4 mv = *(const float4*)&Ms[k][ty * 4];
            u64t m0 = splat2(mv.x), m1 = splat2(mv.y), m2 = splat2(mv.z), m3 = splat2(mv.w);
            const ulonglong2* ep = (const ulonglong2*)&Es[k][tx * 8];
            ulonglong2 e0 = ep[0], e1 = ep[1];
            acc[0]  = fma2(m0, e0.x, acc[0]);  acc[1]  = fma2(m0, e0.y, acc[1]);
            acc[2]  = fma2(m0, e1.x, acc[2]);  acc[3]  = fma2(m0, e1.y, acc[3]);
            acc[4]  = fma2(m1, e0.x, acc[4]);  acc[5]  = fma2(m1, e0.y, acc[5]);
            acc[6]  = fma2(m1, e1.x, acc[6]);  acc[7]  = fma2(m1, e1.y, acc[7]);
            acc[8]  = fma2(m2, e0.x, acc[8]);  acc[9]  = fma2(m2, e0.y, acc[9]);
            acc[10] = fma2(m2, e1.x, acc[10]); acc[11] = fma2(m2, e1.y, acc[11]);
            acc[12] = fma2(m3, e0.x, acc[12]); acc[13] = fma2(m3, e0.y, acc[13]);
            acc[14] = fma2(m3, e1.x, acc[14]); acc[15] = fma2(m3, e1.y, acc[15]);
        }
    }

    const int nbase = n0 + tx * 8;
    if (nbase >= 1000) return;
    #pragma unroll
    for (int r = 0; r < 4; ++r) {
        int p = p0 + ty * 4 + r;
        if (p < 100) {
            int idx = (b * 100 + p) * 1000 + nbase;
            float sv[8];
            #pragma unroll
            for (int c = 0; c < 4; ++c) {
                float2 u = unpack2(acc[r * 4 + c]);
                sv[2 * c] = u.x; sv[2 * c + 1] = u.y;
            }
            float4 cd0 = *(const float4*)(cur_dist + idx);
            float4 cd1 = *(const float4*)(cur_dist + idx + 4);
            float4 nz0 = *(const float4*)(noise + idx);
            float4 nz1 = *(const float4*)(noise + idx + 4);
            float cd[8] = {cd0.x, cd0.y, cd0.z, cd0.w, cd1.x, cd1.y, cd1.z, cd1.w};
            float nz[8] = {nz0.x, nz0.y, nz0.z, nz0.w, nz1.x, nz1.y, nz1.z, nz1.w};
            float res[8];
            #pragma unroll
            for (int j = 0; j < 8; ++j) {
                float heur = -__logf(fmaf(2.f, cd[j], 1e-6f));
                float s    = sv[j] * INV_SQRT_EMB + A_COEF * heur + B_COEF * nz[j];
                res[j]     = tanh_scaled(s, 10.f);
            }
            *(float4*)(out + idx)     = make_float4(res[0], res[1], res[2], res[3]);
            *(float4*)(out + idx + 4) = make_float4(res[4], res[5], res[6], res[7]);
        }
    }
}

// ============================================================================
// Kernel 6: masked in-place row softmax, constant shift M=10.
// ============================================================================
__global__ void softmax_kernel(float* __restrict__ out) {
    const int row = blockIdx.x;
    const int tid = threadIdx.x;
    float* sp = out + row * 1000;

    __shared__ unsigned sbw[32];
    __shared__ float ssum[8];
    if (tid < 32) sbw[tid] = g_bits[row * 32 + tid];
    __syncthreads();

    float e[4], lsum = 0.f;
    #pragma unroll
    for (int t = 0; t < 4; ++t) {
        int n = tid + t * 256;
        float x = 0.f;
        if (n < 1000 && !((sbw[n >> 5] >> (n & 31)) & 1u))
            x = __expf(sp[n] - 10.f);
        e[t] = x; lsum += x;
    }
    #pragma unroll
    for (int o = 16; o; o >>= 1) lsum += __shfl_xor_sync(0xffffffffu, lsum, o);
    if ((tid & 31) == 0) ssum[tid >> 5] = lsum;
    __syncthreads();
    float S = 0.f;
    #pragma unroll
    for (int w = 0; w < 8; ++w) S += ssum[w];

    float inv = 1.f / S;
    #pragma unroll
    for (int t = 0; t < 4; ++t) {
        int n = tid + t * 256;
        if (n < 1000) sp[n] = e[t] * inv;
    }
}

// ============================================================================
extern "C" void kernel_launch(void* const* d_in, const int* in_sizes, int n_in,
                              void* d_out, int out_size) {
    const float* eln      = (const float*)d_in[0];
    const float* loadv    = (const float*)d_in[1];
    const float* timev    = (const float*)d_in[2];
    const float* cur_dist = (const float*)d_in[3];
    const float* ninf     = (const float*)d_in[4];
    const float* noise    = (const float*)d_in[5];
    const float* Enodes   = (const float*)d_in[6];
    const float* Wq       = (const float*)d_in[7];
    const float* Wk       = (const float*)d_in[8];
    const float* Wv       = (const float*)d_in[9];
    const float* Wc       = (const float*)d_in[10];
    const float* bc       = (const float*)d_in[11];
    float* out = (float*)d_out;

    const int KV_SMEM = 128 * 132 * 4;   // 67584 B
    static int s_attr_set = 0;
    if (!s_attr_set) {
        cudaFuncSetAttribute(kv_mma_kernel, cudaFuncAttributeMaxDynamicSharedMemorySize, KV_SMEM);
        s_attr_set = 1;
    }

    bits_kernel<<<25600, 256>>>(ninf);
    wprep_kernel<<<32, 256>>>(Wk, Wv);
    kv_mma_kernel<<<dim3(500, 2), 256, KV_SMEM>>>(Enodes);
    q_kernel<<<400, 128>>>(eln, loadv, timev, Wq);
    attn_kernel<<<dim3(512, 4), 64>>>();
    attn_combine<<<200, 256>>>();
    mh_kernel<<<400, 256>>>(Wc, bc);
    score_kernel<<<dim3(8, 2, 64), 256>>>(Enodes, cur_dist, noise, out);
    softmax_kernel<<<6400, 256>>>(out);
}

// round 8
// speedup vs baseline: 2.4964x; 1.1371x over previous
#include <cuda_runtime.h>
#include <cuda_bf16.h>
#include <math.h>
#include <stdint.h>

#define Bc   64
#define Pc   100
#define Nc   1000
#define EMBc 128

// ---- scratch (__device__ globals; no allocation allowed) ----
__device__ __align__(16) float g_K[Bc * Nc * EMBc];
__device__ __align__(16) float g_V[Bc * Nc * EMBc];
__device__ __align__(16) float g_Q[Bc * Pc * EMBc];
__device__ __align__(16) float g_O[Bc * Pc * EMBc];
__device__ __align__(16) float g_MH[Bc * Pc * EMBc];
__device__ __align__(16) unsigned g_bits[Bc * Pc * 32];
__device__ __align__(16) float g_part[4 * 512 * Pc * 17];
// W in mma.sync B-fragment order: [mat][n(128)][kk(8)][q(4)] x uint4{b0h,b1h,b0l,b1l}
__device__ __align__(16) uint4 g_Wfrag[2 * 128 * 8 * 4];

constexpr double X218   = 3.814697265625e-06;
constexpr float  A_COEF = (float)(1.0 / (1.0 + X218));
constexpr float  B_COEF = (float)(1.0 - 1.0 / (1.0 + X218));
constexpr float  INV_SQRT_EMB = 0.08838834764831845f;
constexpr float  LOG2E = 1.44269504088896340736f;

// ---- packed fp32x2 helpers ----
typedef unsigned long long u64t;
__device__ __forceinline__ u64t fma2(u64t a, u64t b, u64t c) {
    u64t d; asm("fma.rn.f32x2 %0, %1, %2, %3;" : "=l"(d) : "l"(a), "l"(b), "l"(c)); return d;
}
__device__ __forceinline__ u64t splat2(float x) {
    u64t d; asm("mov.b64 %0, {%1, %1};" : "=l"(d) : "f"(x)); return d;
}
__device__ __forceinline__ float2 unpack2(u64t v) {
    float2 r; asm("mov.b64 {%0, %1}, %2;" : "=f"(r.x), "=f"(r.y) : "l"(v)); return r;
}
__device__ __forceinline__ float ex2f(float x) {
    float r; asm("ex2.approx.f32 %0, %1;" : "=f"(r) : "f"(x)); return r;
}
__device__ __forceinline__ float rcpf(float x) {
    float r; asm("rcp.approx.f32 %0, %1;" : "=f"(r) : "f"(x)); return r;
}
__device__ __forceinline__ float tanh_scaled(float x, float scale) {
    float t = ex2f(x * (2.f * LOG2E));
    float num = t - 1.f, den = t + 1.f;
    float r = rcpf(den);
    r = r * (2.f - den * r);
    return num * r * scale;
}

// ---- cp.async ----
__device__ __forceinline__ void cp16(void* dst, const void* src) {
    unsigned d = (unsigned)__cvta_generic_to_shared(dst);
    asm volatile("cp.async.cg.shared.global [%0], [%1], 16;" :: "r"(d), "l"(src));
}
#define CP_COMMIT() asm volatile("cp.async.commit_group;" ::: "memory")

// ---- bf16 split helpers ----
__device__ __forceinline__ unsigned packbf2(float a, float b) {
    __nv_bfloat162 v = __floats2bfloat162_rn(a, b);
    return *reinterpret_cast<unsigned*>(&v);
}
__device__ __forceinline__ float bfrt(float x) {
    return __bfloat162float(__float2bfloat16(x));
}

// ---- mma.sync m16n8k16 bf16, fp32 accum (baseline PTX; HMMA on sm_103) ----
__device__ __forceinline__ void mma16816(float& d0, float& d1, float& d2, float& d3,
                                         unsigned a0, unsigned a1, unsigned a2, unsigned a3,
                                         unsigned b0, unsigned b1) {
    asm volatile(
        "mma.sync.aligned.m16n8k16.row.col.f32.bf16.bf16.f32 "
        "{%0,%1,%2,%3}, {%4,%5,%6,%7}, {%8,%9}, {%0,%1,%2,%3};"
        : "+f"(d0), "+f"(d1), "+f"(d2), "+f"(d3)
        : "r"(a0), "r"(a1), "r"(a2), "r"(a3), "r"(b0), "r"(b1));
}

// ============================================================================
// Kernel 0: pack ninf mask into bits (1 = masked).
// ============================================================================
__global__ void bits_kernel(const float* __restrict__ ninf) {
    const int w = blockIdx.x * 8 + (threadIdx.x >> 5);
    if (w >= Bc * Pc * 32) return;
    const int lane = threadIdx.x & 31;
    const int row = w >> 5, word = w & 31;
    const int n = word * 32 + lane;
    float v = -1.f;
    if (n < 1000) v = ninf[row * 1000 + n];
    unsigned m = __ballot_sync(0xffffffffu, v < -0.5f);
    if (lane == 0) g_bits[w] = m;
}

// ============================================================================
// Kernel 0b: pack W into B-fragment order (hi/lo bf16 split).
// ============================================================================
__global__ void wprep_kernel(const float* __restrict__ Wk, const float* __restrict__ Wv) {
    int idx = blockIdx.x * 256 + threadIdx.x;   // 8192 uint4 entries
    if (idx >= 8192) return;
    const int mat = idx >> 12;
    const int n   = (idx >> 5) & 127;
    const int kk  = (idx >> 2) & 7;
    const int q   = idx & 3;
    const int k   = kk * 16 + q * 2;
    const float* W = mat ? Wv : Wk;
    float w0 = W[k * 128 + n],       w1 = W[(k + 1) * 128 + n];
    float w2 = W[(k + 8) * 128 + n], w3 = W[(k + 9) * 128 + n];
    uint4 v;
    v.x = packbf2(w0, w1);
    v.y = packbf2(w2, w3);
    v.z = packbf2(w0 - bfrt(w0), w1 - bfrt(w1));
    v.w = packbf2(w2 - bfrt(w2), w3 - bfrt(w3));
    g_Wfrag[idx] = v;
}

// ============================================================================
// Kernel 1: K/V = E @ W via mma.sync bf16 hi/lo split (validated round 7).
// ============================================================================
__global__ void __launch_bounds__(256, 2)
kv_mma_kernel(const float* __restrict__ E) {
    extern __shared__ __align__(16) float Es[];   // [128][132]
    const int tid  = threadIdx.x;
    const int wid  = tid >> 5;
    const int lane = tid & 31;
    const int R0   = blockIdx.x * 128;
    const int mat  = blockIdx.y;
    const int wr   = wid >> 1;
    const int wc   = wid & 1;

    for (int l = tid; l < 4096; l += 256) {
        int row = l >> 5, q = l & 31;
        cp16(&Es[row * 132 + q * 4], E + (R0 + row) * 128 + q * 4);
    }
    CP_COMMIT();

    float acc[2][8][4];
    #pragma unroll
    for (int mt = 0; mt < 2; ++mt)
        #pragma unroll
        for (int nt = 0; nt < 8; ++nt)
            #pragma unroll
            for (int i = 0; i < 4; ++i) acc[mt][nt][i] = 0.f;

    const int rfrag = lane >> 2;
    const int cfrag = (lane & 3) * 2;
    const uint4* Wf = g_Wfrag + mat * 4096;

    asm volatile("cp.async.wait_group 0;" ::: "memory");
    __syncthreads();

    #pragma unroll
    for (int kk = 0; kk < 8; ++kk) {
        unsigned ahi[2][4], alo[2][4];
        #pragma unroll
        for (int mt = 0; mt < 2; ++mt) {
            const float* r0p = &Es[(wr * 32 + mt * 16 + rfrag) * 132 + kk * 16 + cfrag];
            const float* r8p = r0p + 8 * 132;
            float2 x0 = *(const float2*)r0p;
            float2 x1 = *(const float2*)r8p;
            float2 x2 = *(const float2*)(r0p + 8);
            float2 x3 = *(const float2*)(r8p + 8);
            ahi[mt][0] = packbf2(x0.x, x0.y);
            ahi[mt][1] = packbf2(x1.x, x1.y);
            ahi[mt][2] = packbf2(x2.x, x2.y);
            ahi[mt][3] = packbf2(x3.x, x3.y);
            alo[mt][0] = packbf2(x0.x - bfrt(x0.x), x0.y - bfrt(x0.y));
            alo[mt][1] = packbf2(x1.x - bfrt(x1.x), x1.y - bfrt(x1.y));
            alo[mt][2] = packbf2(x2.x - bfrt(x2.x), x2.y - bfrt(x2.y));
            alo[mt][3] = packbf2(x3.x - bfrt(x3.x), x3.y - bfrt(x3.y));
        }
        #pragma unroll
        for (int nt = 0; nt < 8; ++nt) {
            const int n = wc * 64 + nt * 8 + rfrag;
            uint4 bf = Wf[(n * 8 + kk) * 4 + (lane & 3)];
            #pragma unroll
            for (int mt = 0; mt < 2; ++mt) {
                mma16816(acc[mt][nt][0], acc[mt][nt][1], acc[mt][nt][2], acc[mt][nt][3],
                         ahi[mt][0], ahi[mt][1], ahi[mt][2], ahi[mt][3], bf.x, bf.y);
                mma16816(acc[mt][nt][0], acc[mt][nt][1], acc[mt][nt][2], acc[mt][nt][3],
                         alo[mt][0], alo[mt][1], alo[mt][2], alo[mt][3], bf.x, bf.y);
                mma16816(acc[mt][nt][0], acc[mt][nt][1], acc[mt][nt][2], acc[mt][nt][3],
                         ahi[mt][0], ahi[mt][1], ahi[mt][2], ahi[mt][3], bf.z, bf.w);
            }
        }
    }

    float* dst = (mat ? g_V : g_K);
    #pragma unroll
    for (int mt = 0; mt < 2; ++mt) {
        const int row = R0 + wr * 32 + mt * 16 + rfrag;
        #pragma unroll
        for (int nt = 0; nt < 8; ++nt) {
            const int col = wc * 64 + nt * 8 + cfrag;
            *(float2*)(dst + (size_t)row * 128 + col)       = make_float2(acc[mt][nt][0], acc[mt][nt][1]);
            *(float2*)(dst + (size_t)(row + 8) * 128 + col) = make_float2(acc[mt][nt][2], acc[mt][nt][3]);
        }
    }
}

// ============================================================================
// Kernel 2: Q = concat(eln, load, time) @ Wq
// ============================================================================
__global__ void q_kernel(const float* __restrict__ eln,
                         const float* __restrict__ loadv,
                         const float* __restrict__ timev,
                         const float* __restrict__ Wq) {
    __shared__ __align__(16) float sA[130][16];
    const int r0  = blockIdx.x * 16;
    const int tid = threadIdx.x;

    for (int l = tid; l < 130 * 16; l += 128) {
        int k = l >> 4, r = l & 15;
        int g = r0 + r;
        float v;
        if (k < 128)       v = eln[g * 128 + k];
        else if (k == 128) v = loadv[g];
        else               v = timev[g];
        sA[k][r] = v;
    }
    __syncthreads();

    const int c = tid;
    float acc[16];
    #pragma unroll
    for (int i = 0; i < 16; ++i) acc[i] = 0.f;

    for (int k = 0; k < 130; ++k) {
        float w = Wq[k * 128 + c];
        float a[16];
        const float4* ap = (const float4*)sA[k];
        ((float4*)a)[0] = ap[0]; ((float4*)a)[1] = ap[1];
        ((float4*)a)[2] = ap[2]; ((float4*)a)[3] = ap[3];
        #pragma unroll
        for (int i = 0; i < 16; ++i) acc[i] = fmaf(a[i], w, acc[i]);
    }
    #pragma unroll
    for (int i = 0; i < 16; ++i) g_Q[(r0 + i) * 128 + c] = acc[i];
}

// ============================================================================
// Kernel 3: attention via mma.sync. block = (bh, split of 256 n), 224 thr
// = 7 warps = 7 m-tiles of 16 q-rows (100 -> 112 padded). Per 64-n tile:
// QK^T 3-term bf16 split -> S frag -> mask+ex2 in regs -> P frag feeds PV
// mma directly (3-term). K/V staged fp32 in double-buffered smem.
// ============================================================================
__global__ void __launch_bounds__(224, 4)
attn_kernel() {
    const int bh    = blockIdx.x;
    const int split = blockIdx.y;
    const int b     = bh >> 3;
    const int h     = bh & 7;
    const int tid   = threadIdx.x;
    const int wid   = tid >> 5;          // m-tile
    const int lane  = tid & 31;
    const int rfrag = lane >> 2;
    const int c2    = (lane & 3) * 2;
    const int nbeg  = split * 256;

    __shared__ __align__(16) float Kt[2][64][20];
    __shared__ __align__(16) float Vt[2][64][20];

    const float* Kbase = g_K + b * 1000 * 128 + h * 16;
    const float* Vbase = g_V + b * 1000 * 128 + h * 16;

    // stage tile 0
    for (int l = tid; l < 256; l += 224) {
        int j = l >> 2, qd = (l & 3) * 4;
        int n = nbeg + j; if (n > 999) n = 999;
        cp16(&Kt[0][j][qd], Kbase + n * 128 + qd);
        cp16(&Vt[0][j][qd], Vbase + n * 128 + qd);
    }
    CP_COMMIT();

    // Q fragment (scaled by 0.25*log2e), hi/lo split
    const int p0  = wid * 16 + rfrag;
    const int p1  = p0 + 8;
    const int pr0 = p0 < 100 ? p0 : 99;
    const int pr1 = p1 < 100 ? p1 : 99;
    unsigned qhi[4], qlo[4];
    {
        const float qs = 0.25f * LOG2E;
        const float* q0p = g_Q + (b * 100 + pr0) * 128 + h * 16;
        const float* q1p = g_Q + (b * 100 + pr1) * 128 + h * 16;
        float2 x0 = *(const float2*)(q0p + c2);
        float2 x1 = *(const float2*)(q1p + c2);
        float2 x2 = *(const float2*)(q0p + c2 + 8);
        float2 x3 = *(const float2*)(q1p + c2 + 8);
        float v0 = x0.x * qs, v1 = x0.y * qs, v2 = x1.x * qs, v3 = x1.y * qs;
        float v4 = x2.x * qs, v5 = x2.y * qs, v6 = x3.x * qs, v7 = x3.y * qs;
        qhi[0] = packbf2(v0, v1); qhi[1] = packbf2(v2, v3);
        qhi[2] = packbf2(v4, v5); qhi[3] = packbf2(v6, v7);
        qlo[0] = packbf2(v0 - bfrt(v0), v1 - bfrt(v1));
        qlo[1] = packbf2(v2 - bfrt(v2), v3 - bfrt(v3));
        qlo[2] = packbf2(v4 - bfrt(v4), v5 - bfrt(v5));
        qlo[3] = packbf2(v6 - bfrt(v6), v7 - bfrt(v7));
    }
    const unsigned* bw0 = g_bits + (b * 100 + pr0) * 32;
    const unsigned* bw1 = g_bits + (b * 100 + pr1) * 32;

    float acc[2][4];
    #pragma unroll
    for (int dt = 0; dt < 2; ++dt)
        #pragma unroll
        for (int i = 0; i < 4; ++i) acc[dt][i] = 0.f;
    float ls0 = 0.f, ls1 = 0.f;

    for (int t = 0; t < 4; ++t) {
        const int s    = t & 1;
        const int base = nbeg + t * 64;

        if (t + 1 < 4) {
            const int ns = 1 - s, nb2 = base + 64;
            for (int l = tid; l < 256; l += 224) {
                int j = l >> 2, qd = (l & 3) * 4;
                int n = nb2 + j; if (n > 999) n = 999;
                cp16(&Kt[ns][j][qd], Kbase + n * 128 + qd);
                cp16(&Vt[ns][j][qd], Vbase + n * 128 + qd);
            }
            CP_COMMIT();
            asm volatile("cp.async.wait_group 1;" ::: "memory");
        } else {
            asm volatile("cp.async.wait_group 0;" ::: "memory");
        }
        __syncthreads();

        const unsigned mw0a = bw0[base >> 5], mw0b = bw0[(base >> 5) + 1];
        const unsigned mw1a = bw1[base >> 5], mw1b = bw1[(base >> 5) + 1];

        #pragma unroll
        for (int kc = 0; kc < 4; ++kc) {
            unsigned phi[4], plo[4];
            #pragma unroll
            for (int jj = 0; jj < 2; ++jj) {
                const int j    = kc * 2 + jj;
                const int trow = j * 8 + rfrag;
                float2 kb0 = *(const float2*)&Kt[s][trow][c2];
                float2 kb1 = *(const float2*)&Kt[s][trow][c2 + 8];
                unsigned kh0 = packbf2(kb0.x, kb0.y);
                unsigned kh1 = packbf2(kb1.x, kb1.y);
                unsigned kl0 = packbf2(kb0.x - bfrt(kb0.x), kb0.y - bfrt(kb0.y));
                unsigned kl1 = packbf2(kb1.x - bfrt(kb1.x), kb1.y - bfrt(kb1.y));
                float d0 = 0.f, d1 = 0.f, d2 = 0.f, d3 = 0.f;
                mma16816(d0, d1, d2, d3, qhi[0], qhi[1], qhi[2], qhi[3], kh0, kh1);
                mma16816(d0, d1, d2, d3, qlo[0], qlo[1], qlo[2], qlo[3], kh0, kh1);
                mma16816(d0, d1, d2, d3, qhi[0], qhi[1], qhi[2], qhi[3], kl0, kl1);

                const int nsel = j * 8 + c2;
                const int gn   = base + nsel;
                const unsigned w0 = (nsel < 32) ? mw0a : mw0b;
                const unsigned w1 = (nsel < 32) ? mw1a : mw1b;
                const int bit = nsel & 31;
                float e0 = ex2f(d0), e1 = ex2f(d1), e2 = ex2f(d2), e3 = ex2f(d3);
                if (((w0 >> bit) & 1u)       || gn >= 1000)     e0 = 0.f;
                if (((w0 >> (bit + 1)) & 1u) || gn + 1 >= 1000) e1 = 0.f;
                if (((w1 >> bit) & 1u)       || gn >= 1000)     e2 = 0.f;
                if (((w1 >> (bit + 1)) & 1u) || gn + 1 >= 1000) e3 = 0.f;
                ls0 += e0 + e1;
                ls1 += e2 + e3;
                phi[2 * jj]     = packbf2(e0, e1);
                phi[2 * jj + 1] = packbf2(e2, e3);
                plo[2 * jj]     = packbf2(e0 - bfrt(e0), e1 - bfrt(e1));
                plo[2 * jj + 1] = packbf2(e2 - bfrt(e2), e3 - bfrt(e3));
            }
            #pragma unroll
            for (int dt = 0; dt < 2; ++dt) {
                const int dcol = dt * 8 + rfrag;
                const int vrow = kc * 16 + c2;
                float v00 = Vt[s][vrow][dcol],     v01 = Vt[s][vrow + 1][dcol];
                float v10 = Vt[s][vrow + 8][dcol], v11 = Vt[s][vrow + 9][dcol];
                unsigned vh0 = packbf2(v00, v01), vh1 = packbf2(v10, v11);
                unsigned vl0 = packbf2(v00 - bfrt(v00), v01 - bfrt(v01));
                unsigned vl1 = packbf2(v10 - bfrt(v10), v11 - bfrt(v11));
                mma16816(acc[dt][0], acc[dt][1], acc[dt][2], acc[dt][3],
                         phi[0], phi[1], phi[2], phi[3], vh0, vh1);
                mma16816(acc[dt][0], acc[dt][1], acc[dt][2], acc[dt][3],
                         plo[0], plo[1], plo[2], plo[3], vh0, vh1);
                mma16816(acc[dt][0], acc[dt][1], acc[dt][2], acc[dt][3],
                         phi[0], phi[1], phi[2], phi[3], vl0, vl1);
            }
        }
        __syncthreads();
    }

    // quad-reduce row sums (lanes in a quad share the same rows)
    ls0 += __shfl_xor_sync(0xffffffffu, ls0, 1);
    ls0 += __shfl_xor_sync(0xffffffffu, ls0, 2);
    ls1 += __shfl_xor_sync(0xffffffffu, ls1, 1);
    ls1 += __shfl_xor_sync(0xffffffffu, ls1, 2);

    if (p0 < 100) {
        float* pp = g_part + ((split * 512 + bh) * 100 + p0) * 17;
        pp[c2]     = acc[0][0]; pp[c2 + 1]     = acc[0][1];
        pp[8 + c2] = acc[1][0]; pp[8 + c2 + 1] = acc[1][1];
        if ((lane & 3) == 0) pp[16] = ls0;
    }
    if (p1 < 100) {
        float* pp = g_part + ((split * 512 + bh) * 100 + p1) * 17;
        pp[c2]     = acc[0][2]; pp[c2 + 1]     = acc[0][3];
        pp[8 + c2] = acc[1][2]; pp[8 + c2 + 1] = acc[1][3];
        if ((lane & 3) == 0) pp[16] = ls1;
    }
}

// ============================================================================
// Kernel 3b: combine 4 attn splits -> g_O
// ============================================================================
__global__ void attn_combine() {
    const int u = blockIdx.x * 256 + threadIdx.x;
    if (u >= 512 * 100) return;
    const int bh = u / 100, p = u % 100;
    float acc[16]; float lsum = 0.f;
    #pragma unroll
    for (int i = 0; i < 16; ++i) acc[i] = 0.f;
    #pragma unroll
    for (int sp = 0; sp < 4; ++sp) {
        const float* pp = g_part + ((sp * 512 + bh) * 100 + p) * 17;
        #pragma unroll
        for (int i = 0; i < 16; ++i) acc[i] += pp[i];
        lsum += pp[16];
    }
    const float inv = 1.f / lsum;
    const int b = bh >> 3, h = bh & 7;
    float* op = g_O + (b * 100 + p) * 128 + h * 16;
    #pragma unroll
    for (int i = 0; i < 16; ++i) op[i] = acc[i] * inv;
}

// ============================================================================
// Kernel 4: MH = O @ Wc + bc
// ============================================================================
__global__ void __launch_bounds__(256)
mh_kernel(const float* __restrict__ Wc, const float* __restrict__ bc) {
    __shared__ float As[128][20];
    const int tid = threadIdx.x;
    const int R0  = blockIdx.x * 16;
    const int tx  = tid & 63;
    const int ty  = tid >> 6;

    for (int l = tid; l < 2048; l += 256) {
        int row = l >> 7, col = l & 127;
        As[col][row] = g_O[(R0 + row) * 128 + col];
    }
    __syncthreads();

    u64t acc[4];
    {
        float2 bb = *(const float2*)(bc + tx * 2);
        u64t bb2; asm("mov.b64 %0, {%1, %2};" : "=l"(bb2) : "f"(bb.x), "f"(bb.y));
        acc[0] = bb2; acc[1] = bb2; acc[2] = bb2; acc[3] = bb2;
    }

    #pragma unroll 8
    for (int k = 0; k < 128; ++k) {
        u64t w = *(const u64t*)(Wc + k * 128 + tx * 2);
        float4 a = *(const float4*)&As[k][ty * 4];
        acc[0] = fma2(splat2(a.x), w, acc[0]);
        acc[1] = fma2(splat2(a.y), w, acc[1]);
        acc[2] = fma2(splat2(a.z), w, acc[2]);
        acc[3] = fma2(splat2(a.w), w, acc[3]);
    }

    #pragma unroll
    for (int r = 0; r < 4; ++r)
        *(u64t*)(g_MH + (R0 + ty * 4 + r) * 128 + tx * 2) = acc[r];
}

// ============================================================================
// Kernel 5: score = MH @ E^T + fused epilogue
// ============================================================================
__global__ void __launch_bounds__(256, 2)
score_kernel(const float* __restrict__ Enodes,
             const float* __restrict__ cur_dist,
             const float* __restrict__ noise,
             float* __restrict__ out) {
    const int b   = blockIdx.z;
    const int p0  = blockIdx.y * 64;
    const int n0  = blockIdx.x * 128;
    const int tid = threadIdx.x;
    const int tx  = tid & 15, ty = tid >> 4;

    __shared__ float Es[32][132];
    __shared__ float Ms[32][68];

    u64t acc[16];
    #pragma unroll
    for (int i = 0; i < 16; ++i) acc[i] = 0ull;

    for (int kc = 0; kc < 128; kc += 32) {
        __syncthreads();
        for (int l = tid; l < 4096; l += 256) {
            int n = l >> 5, k = l & 31;
            Es[k][n] = (n0 + n < 1000) ? Enodes[(b * 1000 + n0 + n) * 128 + kc + k] : 0.f;
        }
        for (int l = tid; l < 2048; l += 256) {
            int pp = l >> 5, k = l & 31;
            int p = p0 + pp;
            Ms[k][pp] = (p < 100) ? g_MH[(b * 100 + p) * 128 + kc + k] : 0.f;
        }
        __syncthreads();

        #pragma unroll 4
        for (int k = 0; k < 32; ++k) {
            float4 mv = *(const float4*)&Ms[k][ty * 4];
            u64t m0 = splat2(mv.x), m1 = splat2(mv.y), m2 = splat2(mv.z), m3 = splat2(mv.w);
            const ulonglong2* ep = (const ulonglong2*)&Es[k][tx * 8];
            ulonglong2 e0 = ep[0], e1 = ep[1];
            acc[0]  = fma2(m0, e0.x, acc[0]);  acc[1]  = fma2(m0, e0.y, acc[1]);
            acc[2]  = fma2(m0, e1.x, acc[2]);  acc[3]  = fma2(m0, e1.y, acc[3]);
            acc[4]  = fma2(m1, e0.x, acc[4]);  acc[5]  = fma2(m1, e0.y, acc[5]);
            acc[6]  = fma2(m1, e1.x, acc[6]);  acc[7]  = fma2(m1, e1.y, acc[7]);
            acc[8]  = fma2(m2, e0.x, acc[8]);  acc[9]  = fma2(m2, e0.y, acc[9]);
            acc[10] = fma2(m2, e1.x, acc[10]); acc[11] = fma2(m2, e1.y, acc[11]);
            acc[12] = fma2(m3, e0.x, acc[12]); acc[13] = fma2(m3, e0.y, acc[13]);
            acc[14] = fma2(m3, e1.x, acc[14]); acc[15] = fma2(m3, e1.y, acc[15]);
        }
    }

    const int nbase = n0 + tx * 8;
    if (nbase >= 1000) return;
    #pragma unroll
    for (int r = 0; r < 4; ++r) {
        int p = p0 + ty * 4 + r;
        if (p < 100) {
            int idx = (b * 100 + p) * 1000 + nbase;
            float sv[8];
            #pragma unroll
            for (int c = 0; c < 4; ++c) {
                float2 u = unpack2(acc[r * 4 + c]);
                sv[2 * c] = u.x; sv[2 * c + 1] = u.y;
            }
            float4 cd0 = *(const float4*)(cur_dist + idx);
            float4 cd1 = *(const float4*)(cur_dist + idx + 4);
            float4 nz0 = *(const float4*)(noise + idx);
            float4 nz1 = *(const float4*)(noise + idx + 4);
            float cd[8] = {cd0.x, cd0.y, cd0.z, cd0.w, cd1.x, cd1.y, cd1.z, cd1.w};
            float nz[8] = {nz0.x, nz0.y, nz0.z, nz0.w, nz1.x, nz1.y, nz1.z, nz1.w};
            float res[8];
            #pragma unroll
            for (int j = 0; j < 8; ++j) {
                float heur = -__logf(fmaf(2.f, cd[j], 1e-6f));
                float s    = sv[j] * INV_SQRT_EMB + A_COEF * heur + B_COEF * nz[j];
                res[j]     = tanh_scaled(s, 10.f);
            }
            *(float4*)(out + idx)     = make_float4(res[0], res[1], res[2], res[3]);
            *(float4*)(out + idx + 4) = make_float4(res[4], res[5], res[6], res[7]);
        }
    }
}

// ============================================================================
// Kernel 6: masked in-place row softmax, constant shift M=10.
// ============================================================================
__global__ void softmax_kernel(float* __restrict__ out) {
    const int row = blockIdx.x;
    const int tid = threadIdx.x;
    float* sp = out + row * 1000;

    __shared__ unsigned sbw[32];
    __shared__ float ssum[8];
    if (tid < 32) sbw[tid] = g_bits[row * 32 + tid];
    __syncthreads();

    float e[4], lsum = 0.f;
    #pragma unroll
    for (int t = 0; t < 4; ++t) {
        int n = tid + t * 256;
        float x = 0.f;
        if (n < 1000 && !((sbw[n >> 5] >> (n & 31)) & 1u))
            x = __expf(sp[n] - 10.f);
        e[t] = x; lsum += x;
    }
    #pragma unroll
    for (int o = 16; o; o >>= 1) lsum += __shfl_xor_sync(0xffffffffu, lsum, o);
    if ((tid & 31) == 0) ssum[tid >> 5] = lsum;
    __syncthreads();
    float S = 0.f;
    #pragma unroll
    for (int w = 0; w < 8; ++w) S += ssum[w];

    float inv = 1.f / S;
    #pragma unroll
    for (int t = 0; t < 4; ++t) {
        int n = tid + t * 256;
        if (n < 1000) sp[n] = e[t] * inv;
    }
}

// ============================================================================
extern "C" void kernel_launch(void* const* d_in, const int* in_sizes, int n_in,
                              void* d_out, int out_size) {
    const float* eln      = (const float*)d_in[0];
    const float* loadv    = (const float*)d_in[1];
    const float* timev    = (const float*)d_in[2];
    const float* cur_dist = (const float*)d_in[3];
    const float* ninf     = (const float*)d_in[4];
    const float* noise    = (const float*)d_in[5];
    const float* Enodes   = (const float*)d_in[6];
    const float* Wq       = (const float*)d_in[7];
    const float* Wk       = (const float*)d_in[8];
    const float* Wv       = (const float*)d_in[9];
    const float* Wc       = (const float*)d_in[10];
    const float* bc       = (const float*)d_in[11];
    float* out = (float*)d_out;

    const int KV_SMEM = 128 * 132 * 4;   // 67584 B
    static int s_attr_set = 0;
    if (!s_attr_set) {
        cudaFuncSetAttribute(kv_mma_kernel, cudaFuncAttributeMaxDynamicSharedMemorySize, KV_SMEM);
        s_attr_set = 1;
    }

    bits_kernel<<<25600, 256>>>(ninf);
    wprep_kernel<<<32, 256>>>(Wk, Wv);
    kv_mma_kernel<<<dim3(500, 2), 256, KV_SMEM>>>(Enodes);
    q_kernel<<<400, 128>>>(eln, loadv, timev, Wq);
    attn_kernel<<<dim3(512, 4), 224>>>();
    attn_combine<<<200, 256>>>();
    mh_kernel<<<400, 256>>>(Wc, bc);
    score_kernel<<<dim3(8, 2, 64), 256>>>(Enodes, cur_dist, noise, out);
    softmax_kernel<<<6400, 256>>>(out);
}